// round 5
// baseline (speedup 1.0000x reference)
#include <cuda_runtime.h>
#include <cuda_bf16.h>
#include <math.h>
#include <math_constants.h>
#include <stdint.h>

#define BATCH  2
#define SDIM   2048
#define DMODEL 1024
#define NHEADS 16
#define HDIM   64
#define MTOT   (BATCH * SDIM)          // 4096
#define SLOTSZ (MTOT * DMODEL)

// ---------------- scratch ----------------
__device__ __nv_bfloat16 g_xhi[SLOTSZ];
__device__ __nv_bfloat16 g_xlo[SLOTSZ];
__device__ __nv_bfloat16 g_qkvh[3 * SLOTSZ];   // slot 0=Q,1=K,2=V  [M,1024]
__device__ __nv_bfloat16 g_qkvl[3 * SLOTSZ];
__device__ __nv_bfloat16 g_ah[SLOTSZ];         // attention out hi/lo
__device__ __nv_bfloat16 g_al[SLOTSZ];
__device__ __nv_bfloat16 g_whi[4 * DMODEL * DMODEL];  // W^T slots: q,k,v,o
__device__ __nv_bfloat16 g_wlo[4 * DMODEL * DMODEL];

// ---------------- PTX helpers ----------------
__device__ __forceinline__ uint32_t smem_u32(const void* p) {
    uint32_t a;
    asm("{ .reg .u64 t; cvta.to.shared.u64 t, %1; cvt.u32.u64 %0, t; }"
        : "=r"(a) : "l"(p));
    return a;
}
__device__ __forceinline__ void cp16(uint32_t dst, const void* src) {
    asm volatile("cp.async.ca.shared.global [%0], [%1], 16;"
                 :: "r"(dst), "l"(src) : "memory");
}
#define CP_COMMIT() asm volatile("cp.async.commit_group;" ::: "memory")
#define CP_WAIT1()  asm volatile("cp.async.wait_group 1;" ::: "memory")
#define CP_WAIT0()  asm volatile("cp.async.wait_group 0;" ::: "memory")

__device__ __forceinline__ void ldm_x4(uint32_t& r0, uint32_t& r1,
                                       uint32_t& r2, uint32_t& r3, uint32_t a) {
    asm volatile("ldmatrix.sync.aligned.m8n8.x4.shared.b16 {%0,%1,%2,%3}, [%4];"
                 : "=r"(r0), "=r"(r1), "=r"(r2), "=r"(r3) : "r"(a));
}
__device__ __forceinline__ void ldm_x4t(uint32_t& r0, uint32_t& r1,
                                        uint32_t& r2, uint32_t& r3, uint32_t a) {
    asm volatile("ldmatrix.sync.aligned.m8n8.x4.trans.shared.b16 {%0,%1,%2,%3}, [%4];"
                 : "=r"(r0), "=r"(r1), "=r"(r2), "=r"(r3) : "r"(a));
}
__device__ __forceinline__ void mma_bf16(float* d, const uint32_t* a,
                                         uint32_t b0, uint32_t b1) {
    asm volatile(
        "mma.sync.aligned.m16n8k16.row.col.f32.bf16.bf16.f32 "
        "{%0,%1,%2,%3}, {%4,%5,%6,%7}, {%8,%9}, {%0,%1,%2,%3};"
        : "+f"(d[0]), "+f"(d[1]), "+f"(d[2]), "+f"(d[3])
        : "r"(a[0]), "r"(a[1]), "r"(a[2]), "r"(a[3]), "r"(b0), "r"(b1));
}
__device__ __forceinline__ uint32_t packbf(float lo, float hi) {
    __nv_bfloat162 t = __floats2bfloat162_rn(lo, hi);
    return *(uint32_t*)&t;
}

// =================================================================
// split fp32 -> (hi, lo) bf16
// =================================================================
__global__ __launch_bounds__(256) void split_kernel(
    const float* __restrict__ in, __nv_bfloat16* __restrict__ hi,
    __nv_bfloat16* __restrict__ lo, int n)
{
    int i = (blockIdx.x * 256 + threadIdx.x) * 4;
    if (i >= n) return;
    float4 v = *(const float4*)(in + i);
    __nv_bfloat16 h0 = __float2bfloat16(v.x), h1 = __float2bfloat16(v.y);
    __nv_bfloat16 h2 = __float2bfloat16(v.z), h3 = __float2bfloat16(v.w);
    hi[i + 0] = h0; hi[i + 1] = h1; hi[i + 2] = h2; hi[i + 3] = h3;
    lo[i + 0] = __float2bfloat16(v.x - __bfloat162float(h0));
    lo[i + 1] = __float2bfloat16(v.y - __bfloat162float(h1));
    lo[i + 2] = __float2bfloat16(v.z - __bfloat162float(h2));
    lo[i + 3] = __float2bfloat16(v.w - __bfloat162float(h3));
}

// =================================================================
// transpose + split: W[K,N] fp32 -> W^T hi/lo [N,K] bf16
// =================================================================
__global__ __launch_bounds__(256) void tsplit_kernel(
    const float* __restrict__ W, __nv_bfloat16* __restrict__ hi,
    __nv_bfloat16* __restrict__ lo)
{
    __shared__ float t[32][33];
    const int nt = blockIdx.x * 32, kt = blockIdx.y * 32;
    const int x = threadIdx.x, y = threadIdx.y;
#pragma unroll
    for (int i = 0; i < 4; i++)
        t[y + i * 8][x] = W[(size_t)(kt + y + i * 8) * DMODEL + nt + x];
    __syncthreads();
#pragma unroll
    for (int i = 0; i < 4; i++) {
        float v = t[x][y + i * 8];
        __nv_bfloat16 h = __float2bfloat16(v);
        size_t o = (size_t)(nt + y + i * 8) * DMODEL + kt + x;
        hi[o] = h; lo[o] = __float2bfloat16(v - __bfloat162float(h));
    }
}

// =================================================================
// split-bf16 GEMM via mma.sync.  CTA 128x128, BK=32, 8 warps (4m x 2n),
// warp tile 32x64.  2-stage cp.async, 2 CTAs/SM.
// MODE 0: fp32 out + bias.  MODE 1: split-bf16 out, QKV slot remap.
// =================================================================
#define ST_MAT (128 * 80)             // 10240 B per matrix per stage
#define ST_SZ  (4 * ST_MAT)           // 40960 B per stage
#define OFF_ALO (1 * ST_MAT)
#define OFF_BHI (2 * ST_MAT)
#define OFF_BLO (3 * ST_MAT)

template <int MODE>
__global__ __launch_bounds__(256, 2) void gemm_mma_kernel(
    const __nv_bfloat16* __restrict__ Ahi, const __nv_bfloat16* __restrict__ Alo,
    const __nv_bfloat16* __restrict__ Bhi, const __nv_bfloat16* __restrict__ Blo,
    const float* __restrict__ bias, float* __restrict__ C,
    __nv_bfloat16* __restrict__ Ch, __nv_bfloat16* __restrict__ Cl,
    int M, int N, int K)
{
    extern __shared__ __align__(128) char smem[];
    const uint32_t sb = smem_u32(smem);
    const int tid = threadIdx.x;
    const int wid = tid >> 5, lane = tid & 31;
    const int wm = wid & 3, wn = wid >> 2;
    const int m0 = blockIdx.y * 128, n0 = blockIdx.x * 128;
    const int lrow = lane & 15, lcolb = (lane >> 4) * 16;

    float acc[2][8][4];
#pragma unroll
    for (int mt = 0; mt < 2; mt++)
#pragma unroll
        for (int nt = 0; nt < 8; nt++)
#pragma unroll
            for (int j = 0; j < 4; j++) acc[mt][nt][j] = 0.f;

    const int nchunks = K >> 5;

    auto issue = [&](int c) {
        const int k0 = c << 5;
        const uint32_t st = sb + (uint32_t)((c & 1) * ST_SZ);
#pragma unroll
        for (int i = 0; i < 2; i++) {
            int idx = tid + i * 256;          // 0..511
            int r = idx >> 2, kc = idx & 3;
            uint32_t so = (uint32_t)(r * 80 + kc * 16);
            size_t goA = (size_t)(m0 + r) * K + k0 + kc * 8;
            size_t goB = (size_t)(n0 + r) * K + k0 + kc * 8;
            cp16(st + so, Ahi + goA);
            cp16(st + OFF_ALO + so, Alo + goA);
            cp16(st + OFF_BHI + so, Bhi + goB);
            cp16(st + OFF_BLO + so, Blo + goB);
        }
        CP_COMMIT();
    };

    issue(0);
    issue(1);

    for (int c = 0; c < nchunks; c++) {
        if (c + 1 < nchunks) CP_WAIT1(); else CP_WAIT0();
        __syncthreads();

        const uint32_t st = sb + (uint32_t)((c & 1) * ST_SZ);
        const uint32_t aHi = st + (uint32_t)((wm * 32 + lrow) * 80) + lcolb;
        const uint32_t aLo = aHi + OFF_ALO;
        const uint32_t bHi = st + OFF_BHI + (uint32_t)((wn * 64 + lrow) * 80) + lcolb;
        const uint32_t bLo = bHi + ST_MAT;

#pragma unroll
        for (int ks = 0; ks < 2; ks++) {
            const uint32_t kb = ks * 32;
            uint32_t ah[2][4], al[2][4];
#pragma unroll
            for (int mt = 0; mt < 2; mt++) {
                ldm_x4(ah[mt][0], ah[mt][1], ah[mt][2], ah[mt][3],
                       aHi + (uint32_t)(mt * 16 * 80) + kb);
                ldm_x4(al[mt][0], al[mt][1], al[mt][2], al[mt][3],
                       aLo + (uint32_t)(mt * 16 * 80) + kb);
            }
#pragma unroll
            for (int g = 0; g < 4; g++) {
                uint32_t h0, h1, h2, h3, l0, l1, l2, l3;
                ldm_x4(h0, h1, h2, h3, bHi + (uint32_t)(g * 16 * 80) + kb);
                ldm_x4(l0, l1, l2, l3, bLo + (uint32_t)(g * 16 * 80) + kb);
#pragma unroll
                for (int mt = 0; mt < 2; mt++) {
                    mma_bf16(acc[mt][2 * g + 0], ah[mt], h0, h2);
                    mma_bf16(acc[mt][2 * g + 0], ah[mt], l0, l2);
                    mma_bf16(acc[mt][2 * g + 0], al[mt], h0, h2);
                    mma_bf16(acc[mt][2 * g + 1], ah[mt], h1, h3);
                    mma_bf16(acc[mt][2 * g + 1], ah[mt], l1, l3);
                    mma_bf16(acc[mt][2 * g + 1], al[mt], h1, h3);
                }
            }
        }
        __syncthreads();
        if (c + 2 < nchunks) issue(c + 2);
    }

    const int rbase = m0 + wm * 32 + (lane >> 2);
    const int cb0 = n0 + wn * 64 + 2 * (lane & 3);
#pragma unroll
    for (int mt = 0; mt < 2; mt++)
#pragma unroll
        for (int nt = 0; nt < 8; nt++) {
            int col = cb0 + nt * 8;
            int r0 = rbase + mt * 16;
            if (MODE == 0) {
                float b0 = bias[col], b1 = bias[col + 1];
                float2 v0 = { acc[mt][nt][0] + b0, acc[mt][nt][1] + b1 };
                float2 v1 = { acc[mt][nt][2] + b0, acc[mt][nt][3] + b1 };
                *(float2*)&C[(size_t)r0 * N + col] = v0;
                *(float2*)&C[(size_t)(r0 + 8) * N + col] = v1;
            } else {
                int slot = col >> 10, coll = col & 1023;
                size_t ob = (size_t)slot * SLOTSZ + (size_t)coll;
#pragma unroll
                for (int half = 0; half < 2; half++) {
                    int rr = r0 + half * 8;
                    float v0 = acc[mt][nt][2 * half], v1 = acc[mt][nt][2 * half + 1];
                    __nv_bfloat16 h0 = __float2bfloat16(v0), h1 = __float2bfloat16(v1);
                    __nv_bfloat162 hp; hp.x = h0; hp.y = h1;
                    __nv_bfloat162 lp;
                    lp.x = __float2bfloat16(v0 - __bfloat162float(h0));
                    lp.y = __float2bfloat16(v1 - __bfloat162float(h1));
                    *(__nv_bfloat162*)&Ch[ob + (size_t)rr * DMODEL] = hp;
                    *(__nv_bfloat162*)&Cl[ob + (size_t)rr * DMODEL] = lp;
                }
            }
        }
}

// =================================================================
// Tensor-core flash attention, split-bf16.
// CTA: 128 queries x one (b,h).  8 warps x 16 q-rows.  K/V tiles 64.
// P packed IN PLACE over score regs -> fits 2 CTAs/SM.
// =================================================================
#define AT_ROW 144
#define AT_MAT (64 * AT_ROW)          // 9216
#define AT_STAGE (4 * AT_MAT)         // 36864
#define ASCALE 0.03125f

__global__ __launch_bounds__(256, 2) void attn_mma_kernel(
    const __nv_bfloat16* __restrict__ qkvh,
    const __nv_bfloat16* __restrict__ qkvl,
    __nv_bfloat16* __restrict__ oh, __nv_bfloat16* __restrict__ ol)
{
    extern __shared__ __align__(128) char smem[];
    const uint32_t sb = smem_u32(smem);
    const int tid = threadIdx.x;
    const int wid = tid >> 5, lane = tid & 31;
    const int q0 = (int)(gridDim.x - 1 - blockIdx.x) * 128;
    const int h = blockIdx.y, b = blockIdx.z;

    const size_t base = (size_t)(b * SDIM) * DMODEL + h * HDIM;
    const __nv_bfloat16* Qh = qkvh + base;
    const __nv_bfloat16* Ql = qkvl + base;
    const __nv_bfloat16* Kh = qkvh + SLOTSZ + base;
    const __nv_bfloat16* Kl = qkvl + SLOTSZ + base;
    const __nv_bfloat16* Vh = qkvh + 2 * SLOTSZ + base;
    const __nv_bfloat16* Vl = qkvl + 2 * SLOTSZ + base;

    // ---- stage Q through smem, extract frags ----
#pragma unroll
    for (int i = 0; i < 4; i++) {
        int idx = tid + i * 256;               // 0..1023
        int r = idx >> 3, c = idx & 7;
        size_t go = (size_t)(q0 + r) * DMODEL + c * 8;
        uint32_t so = (uint32_t)(r * AT_ROW + c * 16);
        cp16(sb + so, Qh + go);
        cp16(sb + 128 * AT_ROW + so, Ql + go);
    }
    CP_COMMIT(); CP_WAIT0();
    __syncthreads();

    uint32_t qhf[4][4], qlf[4][4];
    {
        uint32_t qa = sb + (uint32_t)((wid * 16 + (lane & 15)) * AT_ROW)
                         + (uint32_t)((lane >> 4) * 16);
#pragma unroll
        for (int ks = 0; ks < 4; ks++) {
            ldm_x4(qhf[ks][0], qhf[ks][1], qhf[ks][2], qhf[ks][3], qa + ks * 32);
            ldm_x4(qlf[ks][0], qlf[ks][1], qlf[ks][2], qlf[ks][3],
                   qa + 128 * AT_ROW + ks * 32);
        }
    }
    __syncthreads();

    auto issue = [&](int it) {
        const int k0 = it * 64;
        const uint32_t st = sb + (uint32_t)((it & 1) * AT_STAGE);
#pragma unroll
        for (int i = 0; i < 2; i++) {
            int idx = tid + i * 256;           // 0..511
            int r = idx >> 3, c = idx & 7;
            size_t go = (size_t)(k0 + r) * DMODEL + c * 8;
            uint32_t so = (uint32_t)(r * AT_ROW + c * 16);
            cp16(st + 0 * AT_MAT + so, Kh + go);
            cp16(st + 1 * AT_MAT + so, Kl + go);
            cp16(st + 2 * AT_MAT + so, Vh + go);
            cp16(st + 3 * AT_MAT + so, Vl + go);
        }
        CP_COMMIT();
    };

    float m_r[2] = { -1e30f, -1e30f };
    float l_r[2] = { 0.f, 0.f };
    float oc[8][4];
#pragma unroll
    for (int j = 0; j < 8; j++)
#pragma unroll
        for (int v = 0; v < 4; v++) oc[j][v] = 0.f;

    const int niters = (q0 >> 6) + 2;
    issue(0);
    if (niters > 1) issue(1);

    const int r0g = q0 + wid * 16 + (lane >> 2);
    const int r1g = r0g + 8;
    const int wrow_max = q0 + wid * 16 + 15;

    for (int it = 0; it < niters; it++) {
        if (it + 1 < niters) CP_WAIT1(); else CP_WAIT0();
        __syncthreads();
        const int k0 = it * 64;

        if (k0 <= wrow_max) {
            const uint32_t st = sb + (uint32_t)((it & 1) * AT_STAGE);
            const uint32_t kHi = st + (uint32_t)((lane & 15) * AT_ROW)
                                    + (uint32_t)((lane >> 4) * 16);
            const uint32_t kLo = kHi + AT_MAT;
            const uint32_t vHi = st + 2 * AT_MAT + (uint32_t)((lane & 15) * AT_ROW)
                                    + (uint32_t)((lane >> 4) * 16);
            const uint32_t vLo = vHi + AT_MAT;

            // ---- S = Q @ K^T (split) ----
            float sc[8][4];
#pragma unroll
            for (int j = 0; j < 8; j++)
#pragma unroll
                for (int v = 0; v < 4; v++) sc[j][v] = 0.f;

#pragma unroll
            for (int ks = 0; ks < 4; ks++) {
                uint32_t bh[8][2], bl[8][2];
#pragma unroll
                for (int g = 0; g < 4; g++) {
                    uint32_t r0, r1, r2, r3;
                    ldm_x4(r0, r1, r2, r3, kHi + (uint32_t)(g * 16 * AT_ROW) + ks * 32);
                    bh[2 * g + 0][0] = r0; bh[2 * g + 0][1] = r2;
                    bh[2 * g + 1][0] = r1; bh[2 * g + 1][1] = r3;
                    ldm_x4(r0, r1, r2, r3, kLo + (uint32_t)(g * 16 * AT_ROW) + ks * 32);
                    bl[2 * g + 0][0] = r0; bl[2 * g + 0][1] = r2;
                    bl[2 * g + 1][0] = r1; bl[2 * g + 1][1] = r3;
                }
#pragma unroll
                for (int j = 0; j < 8; j++) {
                    mma_bf16(sc[j], qhf[ks], bh[j][0], bh[j][1]);
                    mma_bf16(sc[j], qhf[ks], bl[j][0], bl[j][1]);
                    mma_bf16(sc[j], qlf[ks], bh[j][0], bh[j][1]);
                }
            }

            // ---- mask + scale ----
            const int cb = k0 + 2 * (lane & 3);
#pragma unroll
            for (int j = 0; j < 8; j++) {
                int c0 = cb + 8 * j, c1 = c0 + 1;
                sc[j][0] = (c0 <= r0g) ? sc[j][0] * ASCALE : -1e30f;
                sc[j][1] = (c1 <= r0g) ? sc[j][1] * ASCALE : -1e30f;
                sc[j][2] = (c0 <= r1g) ? sc[j][2] * ASCALE : -1e30f;
                sc[j][3] = (c1 <= r1g) ? sc[j][3] * ASCALE : -1e30f;
            }

            // ---- online softmax ----
            float mt0 = -1e30f, mt1 = -1e30f;
#pragma unroll
            for (int j = 0; j < 8; j++) {
                mt0 = fmaxf(mt0, fmaxf(sc[j][0], sc[j][1]));
                mt1 = fmaxf(mt1, fmaxf(sc[j][2], sc[j][3]));
            }
            mt0 = fmaxf(mt0, __shfl_xor_sync(0xffffffffu, mt0, 1));
            mt0 = fmaxf(mt0, __shfl_xor_sync(0xffffffffu, mt0, 2));
            mt1 = fmaxf(mt1, __shfl_xor_sync(0xffffffffu, mt1, 1));
            mt1 = fmaxf(mt1, __shfl_xor_sync(0xffffffffu, mt1, 2));
            float mn0 = fmaxf(m_r[0], mt0), mn1 = fmaxf(m_r[1], mt1);
            float a0 = __expf(m_r[0] - mn0), a1 = __expf(m_r[1] - mn1);
            m_r[0] = mn0; m_r[1] = mn1;

            float s0 = 0.f, s1 = 0.f;
            // ---- exp + pack P (hi/lo) IN PLACE over sc ----
#pragma unroll
            for (int j = 0; j < 8; j++) {
                float e0 = __expf(sc[j][0] - mn0);
                float e1 = __expf(sc[j][1] - mn0);
                float e2 = __expf(sc[j][2] - mn1);
                float e3 = __expf(sc[j][3] - mn1);
                s0 += e0 + e1; s1 += e2 + e3;
                float f0 = __bfloat162float(__float2bfloat16(e0));
                float f1 = __bfloat162float(__float2bfloat16(e1));
                float f2 = __bfloat162float(__float2bfloat16(e2));
                float f3 = __bfloat162float(__float2bfloat16(e3));
                sc[j][0] = __uint_as_float(packbf(f0, f1));        // P hi (rows 0-7)
                sc[j][1] = __uint_as_float(packbf(f2, f3));        // P hi (rows 8-15)
                sc[j][2] = __uint_as_float(packbf(e0 - f0, e1 - f1)); // P lo
                sc[j][3] = __uint_as_float(packbf(e2 - f2, e3 - f3));
            }
            l_r[0] = l_r[0] * a0 + s0;
            l_r[1] = l_r[1] * a1 + s1;
#pragma unroll
            for (int j = 0; j < 8; j++) {
                oc[j][0] *= a0; oc[j][1] *= a0;
                oc[j][2] *= a1; oc[j][3] *= a1;
            }

            // ---- O += P @ V (split) ----
#pragma unroll
            for (int ks = 0; ks < 4; ks++) {
                uint32_t vh[8][2], vl[8][2];
#pragma unroll
                for (int g = 0; g < 4; g++) {
                    uint32_t r0, r1, r2, r3;
                    ldm_x4t(r0, r1, r2, r3, vHi + (uint32_t)(ks * 16 * AT_ROW) + g * 32);
                    vh[2 * g + 0][0] = r0; vh[2 * g + 0][1] = r1;
                    vh[2 * g + 1][0] = r2; vh[2 * g + 1][1] = r3;
                    ldm_x4t(r0, r1, r2, r3, vLo + (uint32_t)(ks * 16 * AT_ROW) + g * 32);
                    vl[2 * g + 0][0] = r0; vl[2 * g + 0][1] = r1;
                    vl[2 * g + 1][0] = r2; vl[2 * g + 1][1] = r3;
                }
                uint32_t pah[4] = { __float_as_uint(sc[2 * ks][0]),
                                    __float_as_uint(sc[2 * ks][1]),
                                    __float_as_uint(sc[2 * ks + 1][0]),
                                    __float_as_uint(sc[2 * ks + 1][1]) };
                uint32_t pal[4] = { __float_as_uint(sc[2 * ks][2]),
                                    __float_as_uint(sc[2 * ks][3]),
                                    __float_as_uint(sc[2 * ks + 1][2]),
                                    __float_as_uint(sc[2 * ks + 1][3]) };
#pragma unroll
                for (int j = 0; j < 8; j++) {
                    mma_bf16(oc[j], pah, vh[j][0], vh[j][1]);
                    mma_bf16(oc[j], pah, vl[j][0], vl[j][1]);
                    mma_bf16(oc[j], pal, vh[j][0], vh[j][1]);
                }
            }
        }

        __syncthreads();
        if (it + 2 < niters) issue(it + 2);
    }

    // ---- epilogue ----
    float lt0 = l_r[0];
    lt0 += __shfl_xor_sync(0xffffffffu, lt0, 1);
    lt0 += __shfl_xor_sync(0xffffffffu, lt0, 2);
    float lt1 = l_r[1];
    lt1 += __shfl_xor_sync(0xffffffffu, lt1, 1);
    lt1 += __shfl_xor_sync(0xffffffffu, lt1, 2);
    float inv0 = 1.f / lt0, inv1 = 1.f / lt1;

    size_t ob0 = (size_t)(b * SDIM + r0g) * DMODEL + h * HDIM + 2 * (lane & 3);
    size_t ob1 = ob0 + (size_t)8 * DMODEL;
#pragma unroll
    for (int j = 0; j < 8; j++) {
        float v0 = oc[j][0] * inv0, v1 = oc[j][1] * inv0;
        float v2 = oc[j][2] * inv1, v3 = oc[j][3] * inv1;
        __nv_bfloat16 h0 = __float2bfloat16(v0), h1 = __float2bfloat16(v1);
        __nv_bfloat16 h2 = __float2bfloat16(v2), h3 = __float2bfloat16(v3);
        __nv_bfloat162 hp0; hp0.x = h0; hp0.y = h1;
        __nv_bfloat162 hp1; hp1.x = h2; hp1.y = h3;
        __nv_bfloat162 lp0, lp1;
        lp0.x = __float2bfloat16(v0 - __bfloat162float(h0));
        lp0.y = __float2bfloat16(v1 - __bfloat162float(h1));
        lp1.x = __float2bfloat16(v2 - __bfloat162float(h2));
        lp1.y = __float2bfloat16(v3 - __bfloat162float(h3));
        *(__nv_bfloat162*)&oh[ob0 + 8 * j] = hp0;
        *(__nv_bfloat162*)&ol[ob0 + 8 * j] = lp0;
        *(__nv_bfloat162*)&oh[ob1 + 8 * j] = hp1;
        *(__nv_bfloat162*)&ol[ob1 + 8 * j] = lp1;
    }
}

// =================================================================
extern "C" void kernel_launch(void* const* d_in, const int* in_sizes, int n_in,
                              void* d_out, int out_size)
{
    const float* x  = (const float*)d_in[0];
    const float* Wq = (const float*)d_in[1];
    const float* Wk = (const float*)d_in[2];
    const float* Wv = (const float*)d_in[3];
    const float* Wo = (const float*)d_in[4];
    const float* bo = (const float*)d_in[5];
    float* out = (float*)d_out;

    __nv_bfloat16 *pxh, *pxl, *pqkvh, *pqkvl, *pah, *pal, *pwh, *pwl;
    cudaGetSymbolAddress((void**)&pxh, g_xhi);
    cudaGetSymbolAddress((void**)&pxl, g_xlo);
    cudaGetSymbolAddress((void**)&pqkvh, g_qkvh);
    cudaGetSymbolAddress((void**)&pqkvl, g_qkvl);
    cudaGetSymbolAddress((void**)&pah, g_ah);
    cudaGetSymbolAddress((void**)&pal, g_al);
    cudaGetSymbolAddress((void**)&pwh, g_whi);
    cudaGetSymbolAddress((void**)&pwl, g_wlo);

    const int NEL = MTOT * DMODEL;
    const int WEL = DMODEL * DMODEL;

    split_kernel<<<NEL / (256 * 4), 256>>>(x, pxh, pxl, NEL);
    dim3 tgrid(DMODEL / 32, DMODEL / 32), tblk(32, 8);
    tsplit_kernel<<<tgrid, tblk>>>(Wq, pwh + 0 * WEL, pwl + 0 * WEL);
    tsplit_kernel<<<tgrid, tblk>>>(Wk, pwh + 1 * WEL, pwl + 1 * WEL);
    tsplit_kernel<<<tgrid, tblk>>>(Wv, pwh + 2 * WEL, pwl + 2 * WEL);
    tsplit_kernel<<<tgrid, tblk>>>(Wo, pwh + 3 * WEL, pwl + 3 * WEL);

    const int gsmem = 2 * ST_SZ;   // 81920
    cudaFuncSetAttribute(gemm_mma_kernel<0>,
                         cudaFuncAttributeMaxDynamicSharedMemorySize, gsmem);
    cudaFuncSetAttribute(gemm_mma_kernel<1>,
                         cudaFuncAttributeMaxDynamicSharedMemorySize, gsmem);

    // fused QKV projection: N = 3072, split-bf16 epilogue
    dim3 gq(3 * DMODEL / 128, MTOT / 128);   // (24, 32)
    gemm_mma_kernel<1><<<gq, 256, gsmem>>>(pxh, pxl, pwh, pwl,
                                           nullptr, nullptr, pqkvh, pqkvl,
                                           MTOT, 3 * DMODEL, DMODEL);

    const int asmem = 2 * AT_STAGE;         // 73728
    cudaFuncSetAttribute(attn_mma_kernel,
                         cudaFuncAttributeMaxDynamicSharedMemorySize, asmem);
    dim3 agrid(SDIM / 128, NHEADS, BATCH);  // (16, 16, 2)
    attn_mma_kernel<<<agrid, 256, asmem>>>(pqkvh, pqkvl, pah, pal);

    dim3 go(DMODEL / 128, MTOT / 128);      // (8, 32)
    gemm_mma_kernel<0><<<go, 256, gsmem>>>(pah, pal, pwh + 3 * WEL, pwl + 3 * WEL,
                                           bo, out, nullptr, nullptr,
                                           MTOT, DMODEL, DMODEL);
}

// round 6
// speedup vs baseline: 1.1867x; 1.1867x over previous
#include <cuda_runtime.h>
#include <cuda_fp16.h>
#include <math.h>
#include <math_constants.h>
#include <stdint.h>

#define BATCH  2
#define SDIM   2048
#define DMODEL 1024
#define NHEADS 16
#define HDIM   64
#define MTOT   (BATCH * SDIM)          // 4096
#define SLOTSZ (MTOT * DMODEL)

// ---------------- scratch ----------------
__device__ __half g_xhi[SLOTSZ];
__device__ __half g_xlo[SLOTSZ];
__device__ __half g_qkvh[3 * SLOTSZ];   // slot 0=Q,1=K,2=V  [M,1024]
__device__ __half g_qkvl[3 * SLOTSZ];
__device__ __half g_ah[SLOTSZ];         // attention out hi/lo
__device__ __half g_al[SLOTSZ];
__device__ __half g_whi[4 * DMODEL * DMODEL];  // W^T slots: q,k,v,o
__device__ __half g_wlo[4 * DMODEL * DMODEL];

// ---------------- PTX helpers ----------------
__device__ __forceinline__ uint32_t smem_u32(const void* p) {
    uint32_t a;
    asm("{ .reg .u64 t; cvta.to.shared.u64 t, %1; cvt.u32.u64 %0, t; }"
        : "=r"(a) : "l"(p));
    return a;
}
__device__ __forceinline__ void cp16(uint32_t dst, const void* src) {
    asm volatile("cp.async.ca.shared.global [%0], [%1], 16;"
                 :: "r"(dst), "l"(src) : "memory");
}
#define CP_COMMIT() asm volatile("cp.async.commit_group;" ::: "memory")
#define CP_WAIT1()  asm volatile("cp.async.wait_group 1;" ::: "memory")
#define CP_WAIT0()  asm volatile("cp.async.wait_group 0;" ::: "memory")

__device__ __forceinline__ void ldm_x4(uint32_t& r0, uint32_t& r1,
                                       uint32_t& r2, uint32_t& r3, uint32_t a) {
    asm volatile("ldmatrix.sync.aligned.m8n8.x4.shared.b16 {%0,%1,%2,%3}, [%4];"
                 : "=r"(r0), "=r"(r1), "=r"(r2), "=r"(r3) : "r"(a));
}
__device__ __forceinline__ void ldm_x4t(uint32_t& r0, uint32_t& r1,
                                        uint32_t& r2, uint32_t& r3, uint32_t a) {
    asm volatile("ldmatrix.sync.aligned.m8n8.x4.trans.shared.b16 {%0,%1,%2,%3}, [%4];"
                 : "=r"(r0), "=r"(r1), "=r"(r2), "=r"(r3) : "r"(a));
}
__device__ __forceinline__ void mma_f16(float* d, const uint32_t* a,
                                        uint32_t b0, uint32_t b1) {
    asm volatile(
        "mma.sync.aligned.m16n8k16.row.col.f32.f16.f16.f32 "
        "{%0,%1,%2,%3}, {%4,%5,%6,%7}, {%8,%9}, {%0,%1,%2,%3};"
        : "+f"(d[0]), "+f"(d[1]), "+f"(d[2]), "+f"(d[3])
        : "r"(a[0]), "r"(a[1]), "r"(a[2]), "r"(a[3]), "r"(b0), "r"(b1));
}
__device__ __forceinline__ uint32_t packh(float a, float b) {
    __half2 t = __floats2half2_rn(a, b);
    return *(uint32_t*)&t;
}

// =================================================================
// split fp32 -> (hi, lo) fp16
// =================================================================
__global__ __launch_bounds__(256) void split_kernel(
    const float* __restrict__ in, __half* __restrict__ hi,
    __half* __restrict__ lo, int n)
{
    int i = (blockIdx.x * 256 + threadIdx.x) * 4;
    if (i >= n) return;
    float4 v = *(const float4*)(in + i);
    __half h0 = __float2half(v.x), h1 = __float2half(v.y);
    __half h2 = __float2half(v.z), h3 = __float2half(v.w);
    hi[i + 0] = h0; hi[i + 1] = h1; hi[i + 2] = h2; hi[i + 3] = h3;
    lo[i + 0] = __float2half(v.x - __half2float(h0));
    lo[i + 1] = __float2half(v.y - __half2float(h1));
    lo[i + 2] = __float2half(v.z - __half2float(h2));
    lo[i + 3] = __float2half(v.w - __half2float(h3));
}

// =================================================================
// transpose + split: W[K,N] fp32 -> W^T hi/lo [N,K] fp16
// =================================================================
__global__ __launch_bounds__(256) void tsplit_kernel(
    const float* __restrict__ W, __half* __restrict__ hi,
    __half* __restrict__ lo)
{
    __shared__ float t[32][33];
    const int nt = blockIdx.x * 32, kt = blockIdx.y * 32;
    const int x = threadIdx.x, y = threadIdx.y;
#pragma unroll
    for (int i = 0; i < 4; i++)
        t[y + i * 8][x] = W[(size_t)(kt + y + i * 8) * DMODEL + nt + x];
    __syncthreads();
#pragma unroll
    for (int i = 0; i < 4; i++) {
        float v = t[x][y + i * 8];
        __half h = __float2half(v);
        size_t o = (size_t)(nt + y + i * 8) * DMODEL + kt + x;
        hi[o] = h; lo[o] = __float2half(v - __half2float(h));
    }
}

// =================================================================
// split-fp16 GEMM via mma.sync.  CTA 128x64, BK=32, 8 warps (4m x 2n).
// A split (exact).  B plain fp16 (2 MMA) or +Ah*Blo correction (3 MMA,
// used for the V slot of the QKV gemm).
// MODE 0: fp32 out + bias.  MODE 1: split-fp16 out, QKV slot remap.
// =================================================================
#define ST_A   (128 * 80)             // 10240 B per A matrix
#define ST_B   (64 * 80)              // 5120 B per B matrix
#define ST_SZ  (2 * ST_A + 2 * ST_B)  // 30720 B per stage
#define OFF_ALO ST_A
#define OFF_BHI (2 * ST_A)
#define OFF_BLO (2 * ST_A + ST_B)

template <int MODE>
__global__ __launch_bounds__(256) void gemm_mma_kernel(
    const __half* __restrict__ Ahi, const __half* __restrict__ Alo,
    const __half* __restrict__ Bhi, const __half* __restrict__ Blo,
    const float* __restrict__ bias, float* __restrict__ C,
    __half* __restrict__ Ch, __half* __restrict__ Cl,
    int M, int N, int K)
{
    extern __shared__ __align__(128) char smem[];
    const uint32_t sb = smem_u32(smem);
    const int tid = threadIdx.x;
    const int wid = tid >> 5, lane = tid & 31;
    const int wm = wid & 3, wn = wid >> 2;
    const int m0 = blockIdx.y * 128, n0 = blockIdx.x * 64;
    const int lrow = lane & 15, lcolb = (lane >> 4) * 16;
    const bool use_blo = (MODE == 1) && (n0 >= 2 * DMODEL);   // V slot only

    float acc[2][4][4];
#pragma unroll
    for (int mt = 0; mt < 2; mt++)
#pragma unroll
        for (int nt = 0; nt < 4; nt++)
#pragma unroll
            for (int j = 0; j < 4; j++) acc[mt][nt][j] = 0.f;

    const int nchunks = K >> 5;

    auto issue = [&](int c) {
        const int k0 = c << 5;
        const uint32_t st = sb + (uint32_t)((c & 1) * ST_SZ);
#pragma unroll
        for (int i = 0; i < 2; i++) {
            int idx = tid + i * 256;          // 0..511
            int r = idx >> 2, kc = idx & 3;
            size_t go = (size_t)(m0 + r) * K + k0 + kc * 8;
            uint32_t so = (uint32_t)(r * 80 + kc * 16);
            cp16(st + so, Ahi + go);
            cp16(st + OFF_ALO + so, Alo + go);
        }
        {
            int r = tid >> 2, kc = tid & 3;
            size_t go = (size_t)(n0 + r) * K + k0 + kc * 8;
            uint32_t so = (uint32_t)(r * 80 + kc * 16);
            cp16(st + OFF_BHI + so, Bhi + go);
            if (use_blo) cp16(st + OFF_BLO + so, Blo + go);
        }
        CP_COMMIT();
    };

    issue(0);
    issue(1);

    for (int c = 0; c < nchunks; c++) {
        if (c + 1 < nchunks) CP_WAIT1(); else CP_WAIT0();
        __syncthreads();

        const uint32_t st = sb + (uint32_t)((c & 1) * ST_SZ);
        const uint32_t aHi = st + (uint32_t)((wm * 32 + lrow) * 80) + lcolb;
        const uint32_t aLo = aHi + OFF_ALO;
        const uint32_t bHi = st + OFF_BHI + (uint32_t)((wn * 32 + lrow) * 80) + lcolb;
        const uint32_t bLo = bHi + ST_B;

#pragma unroll
        for (int ks = 0; ks < 2; ks++) {
            const uint32_t kb = ks * 32;
            uint32_t ah[2][4], al[2][4];
#pragma unroll
            for (int mt = 0; mt < 2; mt++) {
                ldm_x4(ah[mt][0], ah[mt][1], ah[mt][2], ah[mt][3],
                       aHi + (uint32_t)(mt * 16 * 80) + kb);
                ldm_x4(al[mt][0], al[mt][1], al[mt][2], al[mt][3],
                       aLo + (uint32_t)(mt * 16 * 80) + kb);
            }
            uint32_t bh[4][2];
#pragma unroll
            for (int g = 0; g < 2; g++) {
                uint32_t r0, r1, r2, r3;
                ldm_x4(r0, r1, r2, r3, bHi + (uint32_t)(g * 16 * 80) + kb);
                bh[2 * g + 0][0] = r0; bh[2 * g + 0][1] = r2;
                bh[2 * g + 1][0] = r1; bh[2 * g + 1][1] = r3;
            }
#pragma unroll
            for (int mt = 0; mt < 2; mt++)
#pragma unroll
                for (int nt = 0; nt < 4; nt++) {
                    mma_f16(acc[mt][nt], ah[mt], bh[nt][0], bh[nt][1]);
                    mma_f16(acc[mt][nt], al[mt], bh[nt][0], bh[nt][1]);
                }
            if (use_blo) {
                uint32_t bl[4][2];
#pragma unroll
                for (int g = 0; g < 2; g++) {
                    uint32_t r0, r1, r2, r3;
                    ldm_x4(r0, r1, r2, r3, bLo + (uint32_t)(g * 16 * 80) + kb);
                    bl[2 * g + 0][0] = r0; bl[2 * g + 0][1] = r2;
                    bl[2 * g + 1][0] = r1; bl[2 * g + 1][1] = r3;
                }
#pragma unroll
                for (int mt = 0; mt < 2; mt++)
#pragma unroll
                    for (int nt = 0; nt < 4; nt++)
                        mma_f16(acc[mt][nt], ah[mt], bl[nt][0], bl[nt][1]);
            }
        }
        __syncthreads();
        if (c + 2 < nchunks) issue(c + 2);
    }

    const int rbase = m0 + wm * 32 + (lane >> 2);
    const int cb0 = n0 + wn * 32 + 2 * (lane & 3);
#pragma unroll
    for (int mt = 0; mt < 2; mt++)
#pragma unroll
        for (int nt = 0; nt < 4; nt++) {
            int col = cb0 + nt * 8;
            int r0 = rbase + mt * 16;
            if (MODE == 0) {
                float b0 = bias[col], b1 = bias[col + 1];
                float2 v0 = { acc[mt][nt][0] + b0, acc[mt][nt][1] + b1 };
                float2 v1 = { acc[mt][nt][2] + b0, acc[mt][nt][3] + b1 };
                *(float2*)&C[(size_t)r0 * N + col] = v0;
                *(float2*)&C[(size_t)(r0 + 8) * N + col] = v1;
            } else {
                int slot = col >> 10, coll = col & 1023;
                size_t ob = (size_t)slot * SLOTSZ + (size_t)coll;
#pragma unroll
                for (int half = 0; half < 2; half++) {
                    int rr = r0 + half * 8;
                    float v0 = acc[mt][nt][2 * half], v1 = acc[mt][nt][2 * half + 1];
                    __half h0 = __float2half(v0), h1 = __float2half(v1);
                    __half2 hp; hp.x = h0; hp.y = h1;
                    __half2 lp;
                    lp.x = __float2half(v0 - __half2float(h0));
                    lp.y = __float2half(v1 - __half2float(h1));
                    *(__half2*)&Ch[ob + (size_t)rr * DMODEL] = hp;
                    *(__half2*)&Cl[ob + (size_t)rr * DMODEL] = lp;
                }
            }
        }
}

// =================================================================
// Tensor-core flash attention, fp16.
// Q split (exact), K plain fp16 (2-MMA scores), V split (3-MMA PV).
// CTA: 128 queries x one (b,h).  8 warps x 16 q-rows.  K/V tiles 64.
// Stage: K | Vh | Vl (3 mats, 27648 B), 2 stages.
// =================================================================
#define AT_ROW 144
#define AT_MAT (64 * AT_ROW)          // 9216
#define AT_STAGE (3 * AT_MAT)         // 27648
#define ASCALE 0.03125f

__global__ __launch_bounds__(256, 1) void attn_mma_kernel(
    const __half* __restrict__ qkvh,
    const __half* __restrict__ qkvl,
    __half* __restrict__ oh, __half* __restrict__ ol)
{
    extern __shared__ __align__(128) char smem[];
    const uint32_t sb = smem_u32(smem);
    const int tid = threadIdx.x;
    const int wid = tid >> 5, lane = tid & 31;
    const int q0 = (int)(gridDim.x - 1 - blockIdx.x) * 128;
    const int h = blockIdx.y, b = blockIdx.z;

    const size_t base = (size_t)(b * SDIM) * DMODEL + h * HDIM;
    const __half* Qh = qkvh + base;
    const __half* Ql = qkvl + base;
    const __half* Kh = qkvh + SLOTSZ + base;
    const __half* Vh = qkvh + 2 * SLOTSZ + base;
    const __half* Vl = qkvl + 2 * SLOTSZ + base;

    // ---- stage Q through smem (overlaps stage areas; consumed before issue) ----
#pragma unroll
    for (int i = 0; i < 4; i++) {
        int idx = tid + i * 256;               // 0..1023
        int r = idx >> 3, c = idx & 7;
        size_t go = (size_t)(q0 + r) * DMODEL + c * 8;
        uint32_t so = (uint32_t)(r * AT_ROW + c * 16);
        cp16(sb + so, Qh + go);
        cp16(sb + 128 * AT_ROW + so, Ql + go);
    }
    CP_COMMIT(); CP_WAIT0();
    __syncthreads();

    uint32_t qhf[4][4], qlf[4][4];
    {
        uint32_t qa = sb + (uint32_t)((wid * 16 + (lane & 15)) * AT_ROW)
                         + (uint32_t)((lane >> 4) * 16);
#pragma unroll
        for (int ks = 0; ks < 4; ks++) {
            ldm_x4(qhf[ks][0], qhf[ks][1], qhf[ks][2], qhf[ks][3], qa + ks * 32);
            ldm_x4(qlf[ks][0], qlf[ks][1], qlf[ks][2], qlf[ks][3],
                   qa + 128 * AT_ROW + ks * 32);
        }
    }
    __syncthreads();

    auto issue = [&](int it) {
        const int k0 = it * 64;
        const uint32_t st = sb + (uint32_t)((it & 1) * AT_STAGE);
#pragma unroll
        for (int i = 0; i < 2; i++) {
            int idx = tid + i * 256;           // 0..511
            int r = idx >> 3, c = idx & 7;
            size_t go = (size_t)(k0 + r) * DMODEL + c * 8;
            uint32_t so = (uint32_t)(r * AT_ROW + c * 16);
            cp16(st + 0 * AT_MAT + so, Kh + go);
            cp16(st + 1 * AT_MAT + so, Vh + go);
            cp16(st + 2 * AT_MAT + so, Vl + go);
        }
        CP_COMMIT();
    };

    float m_r[2] = { -1e30f, -1e30f };
    float l_r[2] = { 0.f, 0.f };
    float oc[8][4];
#pragma unroll
    for (int j = 0; j < 8; j++)
#pragma unroll
        for (int v = 0; v < 4; v++) oc[j][v] = 0.f;

    const int niters = (q0 >> 6) + 2;
    issue(0);
    if (niters > 1) issue(1);

    const int r0g = q0 + wid * 16 + (lane >> 2);
    const int r1g = r0g + 8;
    const int wrow_max = q0 + wid * 16 + 15;

    for (int it = 0; it < niters; it++) {
        if (it + 1 < niters) CP_WAIT1(); else CP_WAIT0();
        __syncthreads();
        const int k0 = it * 64;

        if (k0 <= wrow_max) {
            const uint32_t st = sb + (uint32_t)((it & 1) * AT_STAGE);
            const uint32_t kHi = st + (uint32_t)((lane & 15) * AT_ROW)
                                    + (uint32_t)((lane >> 4) * 16);
            const uint32_t vHi = st + 1 * AT_MAT + (uint32_t)((lane & 15) * AT_ROW)
                                    + (uint32_t)((lane >> 4) * 16);
            const uint32_t vLo = vHi + AT_MAT;

            // ---- S = Q @ K^T (Q split, K plain: 2 MMAs) ----
            float sc[8][4];
#pragma unroll
            for (int j = 0; j < 8; j++)
#pragma unroll
                for (int v = 0; v < 4; v++) sc[j][v] = 0.f;

#pragma unroll
            for (int ks = 0; ks < 4; ks++) {
                uint32_t bh[8][2];
#pragma unroll
                for (int g = 0; g < 4; g++) {
                    uint32_t r0, r1, r2, r3;
                    ldm_x4(r0, r1, r2, r3, kHi + (uint32_t)(g * 16 * AT_ROW) + ks * 32);
                    bh[2 * g + 0][0] = r0; bh[2 * g + 0][1] = r2;
                    bh[2 * g + 1][0] = r1; bh[2 * g + 1][1] = r3;
                }
#pragma unroll
                for (int j = 0; j < 8; j++) {
                    mma_f16(sc[j], qhf[ks], bh[j][0], bh[j][1]);
                    mma_f16(sc[j], qlf[ks], bh[j][0], bh[j][1]);
                }
            }

            // ---- mask + scale ----
            const int cb = k0 + 2 * (lane & 3);
#pragma unroll
            for (int j = 0; j < 8; j++) {
                int c0 = cb + 8 * j, c1 = c0 + 1;
                sc[j][0] = (c0 <= r0g) ? sc[j][0] * ASCALE : -1e30f;
                sc[j][1] = (c1 <= r0g) ? sc[j][1] * ASCALE : -1e30f;
                sc[j][2] = (c0 <= r1g) ? sc[j][2] * ASCALE : -1e30f;
                sc[j][3] = (c1 <= r1g) ? sc[j][3] * ASCALE : -1e30f;
            }

            // ---- online softmax ----
            float mt0 = -1e30f, mt1 = -1e30f;
#pragma unroll
            for (int j = 0; j < 8; j++) {
                mt0 = fmaxf(mt0, fmaxf(sc[j][0], sc[j][1]));
                mt1 = fmaxf(mt1, fmaxf(sc[j][2], sc[j][3]));
            }
            mt0 = fmaxf(mt0, __shfl_xor_sync(0xffffffffu, mt0, 1));
            mt0 = fmaxf(mt0, __shfl_xor_sync(0xffffffffu, mt0, 2));
            mt1 = fmaxf(mt1, __shfl_xor_sync(0xffffffffu, mt1, 1));
            mt1 = fmaxf(mt1, __shfl_xor_sync(0xffffffffu, mt1, 2));
            float mn0 = fmaxf(m_r[0], mt0), mn1 = fmaxf(m_r[1], mt1);
            float a0 = __expf(m_r[0] - mn0), a1 = __expf(m_r[1] - mn1);
            m_r[0] = mn0; m_r[1] = mn1;

            float s0 = 0.f, s1 = 0.f;
            // ---- exp + pack P (hi/lo) IN PLACE over sc ----
#pragma unroll
            for (int j = 0; j < 8; j++) {
                float e0 = __expf(sc[j][0] - mn0);
                float e1 = __expf(sc[j][1] - mn0);
                float e2 = __expf(sc[j][2] - mn1);
                float e3 = __expf(sc[j][3] - mn1);
                s0 += e0 + e1; s1 += e2 + e3;
                float f0 = __half2float(__float2half(e0));
                float f1 = __half2float(__float2half(e1));
                float f2 = __half2float(__float2half(e2));
                float f3 = __half2float(__float2half(e3));
                sc[j][0] = __uint_as_float(packh(f0, f1));            // P hi rows 0-7
                sc[j][1] = __uint_as_float(packh(f2, f3));            // P hi rows 8-15
                sc[j][2] = __uint_as_float(packh(e0 - f0, e1 - f1));  // P lo
                sc[j][3] = __uint_as_float(packh(e2 - f2, e3 - f3));
            }
            l_r[0] = l_r[0] * a0 + s0;
            l_r[1] = l_r[1] * a1 + s1;
#pragma unroll
            for (int j = 0; j < 8; j++) {
                oc[j][0] *= a0; oc[j][1] *= a0;
                oc[j][2] *= a1; oc[j][3] *= a1;
            }

            // ---- O += P @ V (P split, V split: 3 MMAs) ----
#pragma unroll
            for (int ks = 0; ks < 4; ks++) {
                uint32_t vh[8][2], vl[8][2];
#pragma unroll
                for (int g = 0; g < 4; g++) {
                    uint32_t r0, r1, r2, r3;
                    ldm_x4t(r0, r1, r2, r3, vHi + (uint32_t)(ks * 16 * AT_ROW) + g * 32);
                    vh[2 * g + 0][0] = r0; vh[2 * g + 0][1] = r1;
                    vh[2 * g + 1][0] = r2; vh[2 * g + 1][1] = r3;
                    ldm_x4t(r0, r1, r2, r3, vLo + (uint32_t)(ks * 16 * AT_ROW) + g * 32);
                    vl[2 * g + 0][0] = r0; vl[2 * g + 0][1] = r1;
                    vl[2 * g + 1][0] = r2; vl[2 * g + 1][1] = r3;
                }
                uint32_t pah[4] = { __float_as_uint(sc[2 * ks][0]),
                                    __float_as_uint(sc[2 * ks][1]),
                                    __float_as_uint(sc[2 * ks + 1][0]),
                                    __float_as_uint(sc[2 * ks + 1][1]) };
                uint32_t pal[4] = { __float_as_uint(sc[2 * ks][2]),
                                    __float_as_uint(sc[2 * ks][3]),
                                    __float_as_uint(sc[2 * ks + 1][2]),
                                    __float_as_uint(sc[2 * ks + 1][3]) };
#pragma unroll
                for (int j = 0; j < 8; j++) {
                    mma_f16(oc[j], pah, vh[j][0], vh[j][1]);
                    mma_f16(oc[j], pah, vl[j][0], vl[j][1]);
                    mma_f16(oc[j], pal, vh[j][0], vh[j][1]);
                }
            }
        }

        __syncthreads();
        if (it + 2 < niters) issue(it + 2);
    }

    // ---- epilogue ----
    float lt0 = l_r[0];
    lt0 += __shfl_xor_sync(0xffffffffu, lt0, 1);
    lt0 += __shfl_xor_sync(0xffffffffu, lt0, 2);
    float lt1 = l_r[1];
    lt1 += __shfl_xor_sync(0xffffffffu, lt1, 1);
    lt1 += __shfl_xor_sync(0xffffffffu, lt1, 2);
    float inv0 = 1.f / lt0, inv1 = 1.f / lt1;

    size_t ob0 = (size_t)(b * SDIM + r0g) * DMODEL + h * HDIM + 2 * (lane & 3);
    size_t ob1 = ob0 + (size_t)8 * DMODEL;
#pragma unroll
    for (int j = 0; j < 8; j++) {
        float v0 = oc[j][0] * inv0, v1 = oc[j][1] * inv0;
        float v2 = oc[j][2] * inv1, v3 = oc[j][3] * inv1;
        __half h0 = __float2half(v0), h1 = __float2half(v1);
        __half h2 = __float2half(v2), h3 = __float2half(v3);
        __half2 hp0; hp0.x = h0; hp0.y = h1;
        __half2 hp1; hp1.x = h2; hp1.y = h3;
        __half2 lp0, lp1;
        lp0.x = __float2half(v0 - __half2float(h0));
        lp0.y = __float2half(v1 - __half2float(h1));
        lp1.x = __float2half(v2 - __half2float(h2));
        lp1.y = __float2half(v3 - __half2float(h3));
        *(__half2*)&oh[ob0 + 8 * j] = hp0;
        *(__half2*)&ol[ob0 + 8 * j] = lp0;
        *(__half2*)&oh[ob1 + 8 * j] = hp1;
        *(__half2*)&ol[ob1 + 8 * j] = lp1;
    }
}

// =================================================================
extern "C" void kernel_launch(void* const* d_in, const int* in_sizes, int n_in,
                              void* d_out, int out_size)
{
    const float* x  = (const float*)d_in[0];
    const float* Wq = (const float*)d_in[1];
    const float* Wk = (const float*)d_in[2];
    const float* Wv = (const float*)d_in[3];
    const float* Wo = (const float*)d_in[4];
    const float* bo = (const float*)d_in[5];
    float* out = (float*)d_out;

    __half *pxh, *pxl, *pqkvh, *pqkvl, *pah, *pal, *pwh, *pwl;
    cudaGetSymbolAddress((void**)&pxh, g_xhi);
    cudaGetSymbolAddress((void**)&pxl, g_xlo);
    cudaGetSymbolAddress((void**)&pqkvh, g_qkvh);
    cudaGetSymbolAddress((void**)&pqkvl, g_qkvl);
    cudaGetSymbolAddress((void**)&pah, g_ah);
    cudaGetSymbolAddress((void**)&pal, g_al);
    cudaGetSymbolAddress((void**)&pwh, g_whi);
    cudaGetSymbolAddress((void**)&pwl, g_wlo);

    const int NEL = MTOT * DMODEL;
    const int WEL = DMODEL * DMODEL;

    split_kernel<<<NEL / (256 * 4), 256>>>(x, pxh, pxl, NEL);
    dim3 tgrid(DMODEL / 32, DMODEL / 32), tblk(32, 8);
    tsplit_kernel<<<tgrid, tblk>>>(Wq, pwh + 0 * WEL, pwl + 0 * WEL);
    tsplit_kernel<<<tgrid, tblk>>>(Wk, pwh + 1 * WEL, pwl + 1 * WEL);
    tsplit_kernel<<<tgrid, tblk>>>(Wv, pwh + 2 * WEL, pwl + 2 * WEL);
    tsplit_kernel<<<tgrid, tblk>>>(Wo, pwh + 3 * WEL, pwl + 3 * WEL);

    const int gsmem = 2 * ST_SZ;   // 61440
    cudaFuncSetAttribute(gemm_mma_kernel<0>,
                         cudaFuncAttributeMaxDynamicSharedMemorySize, gsmem);
    cudaFuncSetAttribute(gemm_mma_kernel<1>,
                         cudaFuncAttributeMaxDynamicSharedMemorySize, gsmem);

    // fused QKV projection: N = 3072, split-fp16 epilogue
    dim3 gq(3 * DMODEL / 64, MTOT / 128);   // (48, 32)
    gemm_mma_kernel<1><<<gq, 256, gsmem>>>(pxh, pxl, pwh, pwl,
                                           nullptr, nullptr, pqkvh, pqkvl,
                                           MTOT, 3 * DMODEL, DMODEL);

    const int asmem = 2 * AT_STAGE;         // 55296
    cudaFuncSetAttribute(attn_mma_kernel,
                         cudaFuncAttributeMaxDynamicSharedMemorySize, asmem);
    dim3 agrid(SDIM / 128, NHEADS, BATCH);  // (16, 16, 2)
    attn_mma_kernel<<<agrid, 256, asmem>>>(pqkvh, pqkvl, pah, pal);

    dim3 go(DMODEL / 64, MTOT / 128);       // (16, 32)
    gemm_mma_kernel<0><<<go, 256, gsmem>>>(pah, pal, pwh + 3 * WEL, pwl + 3 * WEL,
                                           bo, out, nullptr, nullptr,
                                           MTOT, DMODEL, DMODEL);
}

// round 8
// speedup vs baseline: 1.5334x; 1.2921x over previous
#include <cuda_runtime.h>
#include <cuda_fp16.h>
#include <math.h>
#include <math_constants.h>
#include <stdint.h>

#define BATCH  2
#define SDIM   2048
#define DMODEL 1024
#define NHEADS 16
#define HDIM   64
#define MTOT   (BATCH * SDIM)          // 4096
#define SLOTSZ (MTOT * DMODEL)

// ---------------- scratch ----------------
__device__ __half g_xhi[SLOTSZ];
__device__ __half g_xlo[SLOTSZ];       // only V slot consumes this
__device__ __half g_qkvh[3 * SLOTSZ];  // slot 0=Q,1=K,2=V  [M,1024]
__device__ __half g_qkvl[SLOTSZ];      // V-lo only
__device__ __half g_ah[SLOTSZ];        // attention out (hi only)
__device__ __half g_whi[4 * DMODEL * DMODEL];  // W^T slots: q,k,v,o
__device__ __half g_wvlo[DMODEL * DMODEL];     // Wv lo only

// ---------------- PTX helpers ----------------
__device__ __forceinline__ uint32_t smem_u32(const void* p) {
    uint32_t a;
    asm("{ .reg .u64 t; cvta.to.shared.u64 t, %1; cvt.u32.u64 %0, t; }"
        : "=r"(a) : "l"(p));
    return a;
}
__device__ __forceinline__ void cp16(uint32_t dst, const void* src) {
    asm volatile("cp.async.ca.shared.global [%0], [%1], 16;"
                 :: "r"(dst), "l"(src) : "memory");
}
#define CP_COMMIT() asm volatile("cp.async.commit_group;" ::: "memory")
#define CP_WAIT1()  asm volatile("cp.async.wait_group 1;" ::: "memory")
#define CP_WAIT0()  asm volatile("cp.async.wait_group 0;" ::: "memory")

__device__ __forceinline__ void ldm_x4(uint32_t& r0, uint32_t& r1,
                                       uint32_t& r2, uint32_t& r3, uint32_t a) {
    asm volatile("ldmatrix.sync.aligned.m8n8.x4.shared.b16 {%0,%1,%2,%3}, [%4];"
                 : "=r"(r0), "=r"(r1), "=r"(r2), "=r"(r3) : "r"(a));
}
__device__ __forceinline__ void ldm_x4t(uint32_t& r0, uint32_t& r1,
                                        uint32_t& r2, uint32_t& r3, uint32_t a) {
    asm volatile("ldmatrix.sync.aligned.m8n8.x4.trans.shared.b16 {%0,%1,%2,%3}, [%4];"
                 : "=r"(r0), "=r"(r1), "=r"(r2), "=r"(r3) : "r"(a));
}
__device__ __forceinline__ void mma_f16(float* d, const uint32_t* a,
                                        uint32_t b0, uint32_t b1) {
    asm volatile(
        "mma.sync.aligned.m16n8k16.row.col.f32.f16.f16.f32 "
        "{%0,%1,%2,%3}, {%4,%5,%6,%7}, {%8,%9}, {%0,%1,%2,%3};"
        : "+f"(d[0]), "+f"(d[1]), "+f"(d[2]), "+f"(d[3])
        : "r"(a[0]), "r"(a[1]), "r"(a[2]), "r"(a[3]), "r"(b0), "r"(b1));
}
__device__ __forceinline__ uint32_t packh(float a, float b) {
    __half2 t = __floats2half2_rn(a, b);
    return *(uint32_t*)&t;
}

// =================================================================
// split fp32 -> (hi, lo) fp16
// =================================================================
__global__ __launch_bounds__(256) void split_kernel(
    const float* __restrict__ in, __half* __restrict__ hi,
    __half* __restrict__ lo, int n)
{
    int i = (blockIdx.x * 256 + threadIdx.x) * 4;
    if (i >= n) return;
    float4 v = *(const float4*)(in + i);
    __half h0 = __float2half(v.x), h1 = __float2half(v.y);
    __half h2 = __float2half(v.z), h3 = __float2half(v.w);
    hi[i + 0] = h0; hi[i + 1] = h1; hi[i + 2] = h2; hi[i + 3] = h3;
    lo[i + 0] = __float2half(v.x - __half2float(h0));
    lo[i + 1] = __float2half(v.y - __half2float(h1));
    lo[i + 2] = __float2half(v.z - __half2float(h2));
    lo[i + 3] = __float2half(v.w - __half2float(h3));
}

// =================================================================
// transpose (+optional split): W[K,N] fp32 -> W^T [N,K] fp16
// =================================================================
template <bool WRITE_LO>
__global__ __launch_bounds__(256) void tsplit_kernel(
    const float* __restrict__ W, __half* __restrict__ hi,
    __half* __restrict__ lo)
{
    __shared__ float t[32][33];
    const int nt = blockIdx.x * 32, kt = blockIdx.y * 32;
    const int x = threadIdx.x, y = threadIdx.y;
#pragma unroll
    for (int i = 0; i < 4; i++)
        t[y + i * 8][x] = W[(size_t)(kt + y + i * 8) * DMODEL + nt + x];
    __syncthreads();
#pragma unroll
    for (int i = 0; i < 4; i++) {
        float v = t[x][y + i * 8];
        __half h = __float2half(v);
        size_t o = (size_t)(nt + y + i * 8) * DMODEL + kt + x;
        hi[o] = h;
        if (WRITE_LO) lo[o] = __float2half(v - __half2float(h));
    }
}

// =================================================================
// fp16 GEMM via mma.sync.  CTA 128x64, BK=32, 8 warps (4m x 2n).
// MODE 0 (Wo): plain A x plain B, 1 MMA, fp32 out + bias.
// MODE 1 (QKV): Q,K slots plain (1 MMA); V slot split A + W correction
//               (3 MMA).  fp16 out; lo written for V slot only.
//               NOTE: Blo is V-LOCAL [1024,K]; index with n0-2048.
// =================================================================
#define ST_A   (128 * 80)             // 10240 B per A matrix
#define ST_B   (64 * 80)              // 5120 B per B matrix
#define ST_SZ  (2 * ST_A + 2 * ST_B)  // 30720 B per stage
#define OFF_ALO ST_A
#define OFF_BHI (2 * ST_A)
#define OFF_BLO (2 * ST_A + ST_B)

template <int MODE>
__global__ __launch_bounds__(256) void gemm_mma_kernel(
    const __half* __restrict__ Ahi, const __half* __restrict__ Alo,
    const __half* __restrict__ Bhi, const __half* __restrict__ Blo,
    const float* __restrict__ bias, float* __restrict__ C,
    __half* __restrict__ Ch, __half* __restrict__ Cl,
    int M, int N, int K)
{
    extern __shared__ __align__(128) char smem[];
    const uint32_t sb = smem_u32(smem);
    const int tid = threadIdx.x;
    const int wid = tid >> 5, lane = tid & 31;
    const int wm = wid & 3, wn = wid >> 2;
    const int m0 = blockIdx.y * 128, n0 = blockIdx.x * 64;
    const int lrow = lane & 15, lcolb = (lane >> 4) * 16;
    const bool vslot = (MODE == 1) && (n0 >= 2 * DMODEL);   // split path

    float acc[2][4][4];
#pragma unroll
    for (int mt = 0; mt < 2; mt++)
#pragma unroll
        for (int nt = 0; nt < 4; nt++)
#pragma unroll
            for (int j = 0; j < 4; j++) acc[mt][nt][j] = 0.f;

    const int nchunks = K >> 5;

    auto issue = [&](int c) {
        const int k0 = c << 5;
        const uint32_t st = sb + (uint32_t)((c & 1) * ST_SZ);
#pragma unroll
        for (int i = 0; i < 2; i++) {
            int idx = tid + i * 256;          // 0..511
            int r = idx >> 2, kc = idx & 3;
            size_t go = (size_t)(m0 + r) * K + k0 + kc * 8;
            uint32_t so = (uint32_t)(r * 80 + kc * 16);
            cp16(st + so, Ahi + go);
            if (vslot) cp16(st + OFF_ALO + so, Alo + go);
        }
        {
            int r = tid >> 2, kc = tid & 3;
            size_t go = (size_t)(n0 + r) * K + k0 + kc * 8;
            uint32_t so = (uint32_t)(r * 80 + kc * 16);
            cp16(st + OFF_BHI + so, Bhi + go);
            if (vslot) {
                // Blo (g_wvlo) is V-local [1024,K]: subtract the slot base
                size_t gol = (size_t)(n0 - 2 * DMODEL + r) * K + k0 + kc * 8;
                cp16(st + OFF_BLO + so, Blo + gol);
            }
        }
        CP_COMMIT();
    };

    issue(0);
    issue(1);

    for (int c = 0; c < nchunks; c++) {
        if (c + 1 < nchunks) CP_WAIT1(); else CP_WAIT0();
        __syncthreads();

        const uint32_t st = sb + (uint32_t)((c & 1) * ST_SZ);
        const uint32_t aHi = st + (uint32_t)((wm * 32 + lrow) * 80) + lcolb;
        const uint32_t aLo = aHi + OFF_ALO;
        const uint32_t bHi = st + OFF_BHI + (uint32_t)((wn * 32 + lrow) * 80) + lcolb;
        const uint32_t bLo = bHi + ST_B;

#pragma unroll
        for (int ks = 0; ks < 2; ks++) {
            const uint32_t kb = ks * 32;
            uint32_t ah[2][4];
#pragma unroll
            for (int mt = 0; mt < 2; mt++)
                ldm_x4(ah[mt][0], ah[mt][1], ah[mt][2], ah[mt][3],
                       aHi + (uint32_t)(mt * 16 * 80) + kb);
            uint32_t bh[4][2];
#pragma unroll
            for (int g = 0; g < 2; g++) {
                uint32_t r0, r1, r2, r3;
                ldm_x4(r0, r1, r2, r3, bHi + (uint32_t)(g * 16 * 80) + kb);
                bh[2 * g + 0][0] = r0; bh[2 * g + 0][1] = r2;
                bh[2 * g + 1][0] = r1; bh[2 * g + 1][1] = r3;
            }
#pragma unroll
            for (int mt = 0; mt < 2; mt++)
#pragma unroll
                for (int nt = 0; nt < 4; nt++)
                    mma_f16(acc[mt][nt], ah[mt], bh[nt][0], bh[nt][1]);

            if (vslot) {
                uint32_t al[2][4];
#pragma unroll
                for (int mt = 0; mt < 2; mt++)
                    ldm_x4(al[mt][0], al[mt][1], al[mt][2], al[mt][3],
                           aLo + (uint32_t)(mt * 16 * 80) + kb);
                uint32_t bl[4][2];
#pragma unroll
                for (int g = 0; g < 2; g++) {
                    uint32_t r0, r1, r2, r3;
                    ldm_x4(r0, r1, r2, r3, bLo + (uint32_t)(g * 16 * 80) + kb);
                    bl[2 * g + 0][0] = r0; bl[2 * g + 0][1] = r2;
                    bl[2 * g + 1][0] = r1; bl[2 * g + 1][1] = r3;
                }
#pragma unroll
                for (int mt = 0; mt < 2; mt++)
#pragma unroll
                    for (int nt = 0; nt < 4; nt++) {
                        mma_f16(acc[mt][nt], al[mt], bh[nt][0], bh[nt][1]);
                        mma_f16(acc[mt][nt], ah[mt], bl[nt][0], bl[nt][1]);
                    }
            }
        }
        __syncthreads();
        if (c + 2 < nchunks) issue(c + 2);
    }

    const int rbase = m0 + wm * 32 + (lane >> 2);
    const int cb0 = n0 + wn * 32 + 2 * (lane & 3);
#pragma unroll
    for (int mt = 0; mt < 2; mt++)
#pragma unroll
        for (int nt = 0; nt < 4; nt++) {
            int col = cb0 + nt * 8;
            int r0 = rbase + mt * 16;
            if (MODE == 0) {
                float b0 = bias[col], b1 = bias[col + 1];
                float2 v0 = { acc[mt][nt][0] + b0, acc[mt][nt][1] + b1 };
                float2 v1 = { acc[mt][nt][2] + b0, acc[mt][nt][3] + b1 };
                *(float2*)&C[(size_t)r0 * N + col] = v0;
                *(float2*)&C[(size_t)(r0 + 8) * N + col] = v1;
            } else {
                int slot = col >> 10, coll = col & 1023;
                size_t obh = (size_t)slot * SLOTSZ + (size_t)coll;
#pragma unroll
                for (int half = 0; half < 2; half++) {
                    int rr = r0 + half * 8;
                    float v0 = acc[mt][nt][2 * half], v1 = acc[mt][nt][2 * half + 1];
                    __half h0 = __float2half(v0), h1 = __float2half(v1);
                    __half2 hp; hp.x = h0; hp.y = h1;
                    *(__half2*)&Ch[obh + (size_t)rr * DMODEL] = hp;
                    if (vslot) {
                        __half2 lp;
                        lp.x = __float2half(v0 - __half2float(h0));
                        lp.y = __float2half(v1 - __half2float(h1));
                        *(__half2*)&Cl[(size_t)coll + (size_t)rr * DMODEL] = lp;
                    }
                }
            }
        }
}

// =================================================================
// Tensor-core flash attention, fp16.
// Scores: Q plain x K plain (1 MMA).  PV: P plain, V split (2 MMA).
// CTA: 128 queries x one (b,h).  8 warps x 16 q-rows.  K/V tiles 64.
// Stage: K | Vh | Vl (3 mats, 27648 B), 2 stages.
// =================================================================
#define AT_ROW 144
#define AT_MAT (64 * AT_ROW)          // 9216
#define AT_STAGE (3 * AT_MAT)         // 27648
#define ASCALE 0.03125f

__global__ __launch_bounds__(256, 1) void attn_mma_kernel(
    const __half* __restrict__ qkvh,
    const __half* __restrict__ vlo,
    __half* __restrict__ oh)
{
    extern __shared__ __align__(128) char smem[];
    const uint32_t sb = smem_u32(smem);
    const int tid = threadIdx.x;
    const int wid = tid >> 5, lane = tid & 31;
    const int q0 = (int)(gridDim.x - 1 - blockIdx.x) * 128;
    const int h = blockIdx.y, b = blockIdx.z;

    const size_t base = (size_t)(b * SDIM) * DMODEL + h * HDIM;
    const __half* Qh = qkvh + base;
    const __half* Kh = qkvh + SLOTSZ + base;
    const __half* Vh = qkvh + 2 * SLOTSZ + base;
    const __half* Vl = vlo + base;

    // ---- stage Q through smem, extract frags ----
#pragma unroll
    for (int i = 0; i < 2; i++) {
        int idx = tid + i * 256;               // 0..511
        int r = idx >> 2, c = idx & 3;
        size_t go = (size_t)(q0 + r) * DMODEL + c * 16;
        uint32_t so = (uint32_t)(r * AT_ROW + c * 32);
        cp16(sb + so, Qh + go);
        cp16(sb + so + 16, Qh + go + 8);
    }
    CP_COMMIT(); CP_WAIT0();
    __syncthreads();

    uint32_t qf[4][4];
    {
        uint32_t qa = sb + (uint32_t)((wid * 16 + (lane & 15)) * AT_ROW)
                         + (uint32_t)((lane >> 4) * 16);
#pragma unroll
        for (int ks = 0; ks < 4; ks++)
            ldm_x4(qf[ks][0], qf[ks][1], qf[ks][2], qf[ks][3], qa + ks * 32);
    }
    __syncthreads();

    auto issue = [&](int it) {
        const int k0 = it * 64;
        const uint32_t st = sb + (uint32_t)((it & 1) * AT_STAGE);
#pragma unroll
        for (int i = 0; i < 2; i++) {
            int idx = tid + i * 256;           // 0..511
            int r = idx >> 3, c = idx & 7;
            size_t go = (size_t)(k0 + r) * DMODEL + c * 8;
            uint32_t so = (uint32_t)(r * AT_ROW + c * 16);
            cp16(st + 0 * AT_MAT + so, Kh + go);
            cp16(st + 1 * AT_MAT + so, Vh + go);
            cp16(st + 2 * AT_MAT + so, Vl + go);
        }
        CP_COMMIT();
    };

    float m_r[2] = { -1e30f, -1e30f };
    float l_r[2] = { 0.f, 0.f };
    float oc[8][4];
#pragma unroll
    for (int j = 0; j < 8; j++)
#pragma unroll
        for (int v = 0; v < 4; v++) oc[j][v] = 0.f;

    const int niters = (q0 >> 6) + 2;
    issue(0);
    if (niters > 1) issue(1);

    const int r0g = q0 + wid * 16 + (lane >> 2);
    const int r1g = r0g + 8;
    const int wrow_max = q0 + wid * 16 + 15;

    for (int it = 0; it < niters; it++) {
        if (it + 1 < niters) CP_WAIT1(); else CP_WAIT0();
        __syncthreads();
        const int k0 = it * 64;

        if (k0 <= wrow_max) {
            const uint32_t st = sb + (uint32_t)((it & 1) * AT_STAGE);
            const uint32_t kHi = st + (uint32_t)((lane & 15) * AT_ROW)
                                    + (uint32_t)((lane >> 4) * 16);
            const uint32_t vHi = st + 1 * AT_MAT + (uint32_t)((lane & 15) * AT_ROW)
                                    + (uint32_t)((lane >> 4) * 16);
            const uint32_t vLo = vHi + AT_MAT;

            // ---- S = Q @ K^T (plain, 1 MMA) ----
            float sc[8][4];
#pragma unroll
            for (int j = 0; j < 8; j++)
#pragma unroll
                for (int v = 0; v < 4; v++) sc[j][v] = 0.f;

#pragma unroll
            for (int ks = 0; ks < 4; ks++) {
                uint32_t bh[8][2];
#pragma unroll
                for (int g = 0; g < 4; g++) {
                    uint32_t r0, r1, r2, r3;
                    ldm_x4(r0, r1, r2, r3, kHi + (uint32_t)(g * 16 * AT_ROW) + ks * 32);
                    bh[2 * g + 0][0] = r0; bh[2 * g + 0][1] = r2;
                    bh[2 * g + 1][0] = r1; bh[2 * g + 1][1] = r3;
                }
#pragma unroll
                for (int j = 0; j < 8; j++)
                    mma_f16(sc[j], qf[ks], bh[j][0], bh[j][1]);
            }

            // ---- mask + scale ----
            const int cb = k0 + 2 * (lane & 3);
#pragma unroll
            for (int j = 0; j < 8; j++) {
                int c0 = cb + 8 * j, c1 = c0 + 1;
                sc[j][0] = (c0 <= r0g) ? sc[j][0] * ASCALE : -1e30f;
                sc[j][1] = (c1 <= r0g) ? sc[j][1] * ASCALE : -1e30f;
                sc[j][2] = (c0 <= r1g) ? sc[j][2] * ASCALE : -1e30f;
                sc[j][3] = (c1 <= r1g) ? sc[j][3] * ASCALE : -1e30f;
            }

            // ---- online softmax ----
            float mt0 = -1e30f, mt1 = -1e30f;
#pragma unroll
            for (int j = 0; j < 8; j++) {
                mt0 = fmaxf(mt0, fmaxf(sc[j][0], sc[j][1]));
                mt1 = fmaxf(mt1, fmaxf(sc[j][2], sc[j][3]));
            }
            mt0 = fmaxf(mt0, __shfl_xor_sync(0xffffffffu, mt0, 1));
            mt0 = fmaxf(mt0, __shfl_xor_sync(0xffffffffu, mt0, 2));
            mt1 = fmaxf(mt1, __shfl_xor_sync(0xffffffffu, mt1, 1));
            mt1 = fmaxf(mt1, __shfl_xor_sync(0xffffffffu, mt1, 2));
            float mn0 = fmaxf(m_r[0], mt0), mn1 = fmaxf(m_r[1], mt1);
            float a0 = __expf(m_r[0] - mn0), a1 = __expf(m_r[1] - mn1);
            m_r[0] = mn0; m_r[1] = mn1;

            float s0 = 0.f, s1 = 0.f;
            // ---- exp + pack plain P IN PLACE over sc ----
#pragma unroll
            for (int j = 0; j < 8; j++) {
                float e0 = __expf(sc[j][0] - mn0);
                float e1 = __expf(sc[j][1] - mn0);
                float e2 = __expf(sc[j][2] - mn1);
                float e3 = __expf(sc[j][3] - mn1);
                s0 += e0 + e1; s1 += e2 + e3;
                sc[j][0] = __uint_as_float(packh(e0, e1));   // P rows 0-7
                sc[j][1] = __uint_as_float(packh(e2, e3));   // P rows 8-15
            }
            l_r[0] = l_r[0] * a0 + s0;
            l_r[1] = l_r[1] * a1 + s1;
#pragma unroll
            for (int j = 0; j < 8; j++) {
                oc[j][0] *= a0; oc[j][1] *= a0;
                oc[j][2] *= a1; oc[j][3] *= a1;
            }

            // ---- O += P @ V (P plain, V split: 2 MMAs) ----
#pragma unroll
            for (int ks = 0; ks < 4; ks++) {
                uint32_t vh[8][2], vl[8][2];
#pragma unroll
                for (int g = 0; g < 4; g++) {
                    uint32_t r0, r1, r2, r3;
                    ldm_x4t(r0, r1, r2, r3, vHi + (uint32_t)(ks * 16 * AT_ROW) + g * 32);
                    vh[2 * g + 0][0] = r0; vh[2 * g + 0][1] = r1;
                    vh[2 * g + 1][0] = r2; vh[2 * g + 1][1] = r3;
                    ldm_x4t(r0, r1, r2, r3, vLo + (uint32_t)(ks * 16 * AT_ROW) + g * 32);
                    vl[2 * g + 0][0] = r0; vl[2 * g + 0][1] = r1;
                    vl[2 * g + 1][0] = r2; vl[2 * g + 1][1] = r3;
                }
                uint32_t pa[4] = { __float_as_uint(sc[2 * ks][0]),
                                   __float_as_uint(sc[2 * ks][1]),
                                   __float_as_uint(sc[2 * ks + 1][0]),
                                   __float_as_uint(sc[2 * ks + 1][1]) };
#pragma unroll
                for (int j = 0; j < 8; j++) {
                    mma_f16(oc[j], pa, vh[j][0], vh[j][1]);
                    mma_f16(oc[j], pa, vl[j][0], vl[j][1]);
                }
            }
        }

        __syncthreads();
        if (it + 2 < niters) issue(it + 2);
    }

    // ---- epilogue (hi only) ----
    float lt0 = l_r[0];
    lt0 += __shfl_xor_sync(0xffffffffu, lt0, 1);
    lt0 += __shfl_xor_sync(0xffffffffu, lt0, 2);
    float lt1 = l_r[1];
    lt1 += __shfl_xor_sync(0xffffffffu, lt1, 1);
    lt1 += __shfl_xor_sync(0xffffffffu, lt1, 2);
    float inv0 = 1.f / lt0, inv1 = 1.f / lt1;

    size_t ob0 = (size_t)(b * SDIM + r0g) * DMODEL + h * HDIM + 2 * (lane & 3);
    size_t ob1 = ob0 + (size_t)8 * DMODEL;
#pragma unroll
    for (int j = 0; j < 8; j++) {
        __half2 hp0 = __floats2half2_rn(oc[j][0] * inv0, oc[j][1] * inv0);
        __half2 hp1 = __floats2half2_rn(oc[j][2] * inv1, oc[j][3] * inv1);
        *(__half2*)&oh[ob0 + 8 * j] = hp0;
        *(__half2*)&oh[ob1 + 8 * j] = hp1;
    }
}

// =================================================================
extern "C" void kernel_launch(void* const* d_in, const int* in_sizes, int n_in,
                              void* d_out, int out_size)
{
    const float* x  = (const float*)d_in[0];
    const float* Wq = (const float*)d_in[1];
    const float* Wk = (const float*)d_in[2];
    const float* Wv = (const float*)d_in[3];
    const float* Wo = (const float*)d_in[4];
    const float* bo = (const float*)d_in[5];
    float* out = (float*)d_out;

    __half *pxh, *pxl, *pqkvh, *pqkvl, *pah, *pwh, *pwvlo;
    cudaGetSymbolAddress((void**)&pxh, g_xhi);
    cudaGetSymbolAddress((void**)&pxl, g_xlo);
    cudaGetSymbolAddress((void**)&pqkvh, g_qkvh);
    cudaGetSymbolAddress((void**)&pqkvl, g_qkvl);
    cudaGetSymbolAddress((void**)&pah, g_ah);
    cudaGetSymbolAddress((void**)&pwh, g_whi);
    cudaGetSymbolAddress((void**)&pwvlo, g_wvlo);

    const int NEL = MTOT * DMODEL;
    const int WEL = DMODEL * DMODEL;

    split_kernel<<<NEL / (256 * 4), 256>>>(x, pxh, pxl, NEL);
    dim3 tgrid(DMODEL / 32, DMODEL / 32), tblk(32, 8);
    tsplit_kernel<false><<<tgrid, tblk>>>(Wq, pwh + 0 * WEL, nullptr);
    tsplit_kernel<false><<<tgrid, tblk>>>(Wk, pwh + 1 * WEL, nullptr);
    tsplit_kernel<true ><<<tgrid, tblk>>>(Wv, pwh + 2 * WEL, pwvlo);
    tsplit_kernel<false><<<tgrid, tblk>>>(Wo, pwh + 3 * WEL, nullptr);

    const int gsmem = 2 * ST_SZ;   // 61440
    cudaFuncSetAttribute(gemm_mma_kernel<0>,
                         cudaFuncAttributeMaxDynamicSharedMemorySize, gsmem);
    cudaFuncSetAttribute(gemm_mma_kernel<1>,
                         cudaFuncAttributeMaxDynamicSharedMemorySize, gsmem);

    // fused QKV projection: N = 3072
    dim3 gq(3 * DMODEL / 64, MTOT / 128);   // (48, 32)
    gemm_mma_kernel<1><<<gq, 256, gsmem>>>(pxh, pxl, pwh, pwvlo,
                                           nullptr, nullptr, pqkvh, pqkvl,
                                           MTOT, 3 * DMODEL, DMODEL);

    const int asmem = 2 * AT_STAGE;         // 55296
    cudaFuncSetAttribute(attn_mma_kernel,
                         cudaFuncAttributeMaxDynamicSharedMemorySize, asmem);
    dim3 agrid(SDIM / 128, NHEADS, BATCH);  // (16, 16, 2)
    attn_mma_kernel<<<agrid, 256, asmem>>>(pqkvh, pqkvl, pah);

    dim3 go(DMODEL / 64, MTOT / 128);       // (16, 32)
    gemm_mma_kernel<0><<<go, 256, gsmem>>>(pah, nullptr, pwh + 3 * WEL, nullptr,
                                           bo, out, nullptr, nullptr,
                                           MTOT, DMODEL, DMODEL);
}

// round 9
// speedup vs baseline: 1.6021x; 1.0448x over previous
#include <cuda_runtime.h>
#include <cuda_fp16.h>
#include <math.h>
#include <math_constants.h>
#include <stdint.h>

#define BATCH  2
#define SDIM   2048
#define DMODEL 1024
#define NHEADS 16
#define HDIM   64
#define MTOT   (BATCH * SDIM)          // 4096
#define SLOTSZ (MTOT * DMODEL)
#define WEL    (DMODEL * DMODEL)

// ---------------- scratch ----------------
__device__ __half g_xhi[SLOTSZ];
__device__ __half g_xlo[SLOTSZ];       // only V slot consumes this
__device__ __half g_qkvh[3 * SLOTSZ];  // slot 0=Q,1=K,2=V  [M,1024]
__device__ __half g_qkvl[SLOTSZ];      // V-lo only
__device__ __half g_ah[SLOTSZ];        // attention out (hi only)
__device__ __half g_whi[4 * WEL];      // W^T slots: q,k,v,o
__device__ __half g_wvlo[WEL];         // Wv lo only

// ---------------- PTX helpers ----------------
__device__ __forceinline__ uint32_t smem_u32(const void* p) {
    uint32_t a;
    asm("{ .reg .u64 t; cvta.to.shared.u64 t, %1; cvt.u32.u64 %0, t; }"
        : "=r"(a) : "l"(p));
    return a;
}
__device__ __forceinline__ void cp16(uint32_t dst, const void* src) {
    asm volatile("cp.async.ca.shared.global [%0], [%1], 16;"
                 :: "r"(dst), "l"(src) : "memory");
}
#define CP_COMMIT() asm volatile("cp.async.commit_group;" ::: "memory")
#define CP_WAIT1()  asm volatile("cp.async.wait_group 1;" ::: "memory")
#define CP_WAIT0()  asm volatile("cp.async.wait_group 0;" ::: "memory")

__device__ __forceinline__ void ldm_x4(uint32_t& r0, uint32_t& r1,
                                       uint32_t& r2, uint32_t& r3, uint32_t a) {
    asm volatile("ldmatrix.sync.aligned.m8n8.x4.shared.b16 {%0,%1,%2,%3}, [%4];"
                 : "=r"(r0), "=r"(r1), "=r"(r2), "=r"(r3) : "r"(a));
}
__device__ __forceinline__ void ldm_x4t(uint32_t& r0, uint32_t& r1,
                                        uint32_t& r2, uint32_t& r3, uint32_t a) {
    asm volatile("ldmatrix.sync.aligned.m8n8.x4.trans.shared.b16 {%0,%1,%2,%3}, [%4];"
                 : "=r"(r0), "=r"(r1), "=r"(r2), "=r"(r3) : "r"(a));
}
__device__ __forceinline__ void mma_f16(float* d, const uint32_t* a,
                                        uint32_t b0, uint32_t b1) {
    asm volatile(
        "mma.sync.aligned.m16n8k16.row.col.f32.f16.f16.f32 "
        "{%0,%1,%2,%3}, {%4,%5,%6,%7}, {%8,%9}, {%0,%1,%2,%3};"
        : "+f"(d[0]), "+f"(d[1]), "+f"(d[2]), "+f"(d[3])
        : "r"(a[0]), "r"(a[1]), "r"(a[2]), "r"(a[3]), "r"(b0), "r"(b1));
}
__device__ __forceinline__ uint32_t packh(float a, float b) {
    __half2 t = __floats2half2_rn(a, b);
    return *(uint32_t*)&t;
}

// =================================================================
// split fp32 -> (hi, lo) fp16
// =================================================================
__global__ __launch_bounds__(256) void split_kernel(
    const float* __restrict__ in, __half* __restrict__ hi,
    __half* __restrict__ lo, int n)
{
    int i = (blockIdx.x * 256 + threadIdx.x) * 4;
    if (i >= n) return;
    float4 v = *(const float4*)(in + i);
    __half h0 = __float2half(v.x), h1 = __float2half(v.y);
    __half h2 = __float2half(v.z), h3 = __float2half(v.w);
    hi[i + 0] = h0; hi[i + 1] = h1; hi[i + 2] = h2; hi[i + 3] = h3;
    lo[i + 0] = __float2half(v.x - __half2float(h0));
    lo[i + 1] = __float2half(v.y - __half2float(h1));
    lo[i + 2] = __float2half(v.z - __half2float(h2));
    lo[i + 3] = __float2half(v.w - __half2float(h3));
}

// =================================================================
// batched transpose: all 4 weights in one launch (z selects W).
// W[K,N] fp32 -> W^T [N,K] fp16; lo written for Wv (z==2) only.
// =================================================================
__global__ __launch_bounds__(256) void tsplit_all_kernel(
    const float* __restrict__ Wq, const float* __restrict__ Wk,
    const float* __restrict__ Wv, const float* __restrict__ Wo,
    __half* __restrict__ hibase, __half* __restrict__ vlo)
{
    const int z = blockIdx.z;
    const float* W = (z == 0) ? Wq : (z == 1) ? Wk : (z == 2) ? Wv : Wo;
    __half* hi = hibase + (size_t)z * WEL;
    const bool wlo = (z == 2);

    __shared__ float t[32][33];
    const int nt = blockIdx.x * 32, kt = blockIdx.y * 32;
    const int x = threadIdx.x, y = threadIdx.y;
#pragma unroll
    for (int i = 0; i < 4; i++)
        t[y + i * 8][x] = W[(size_t)(kt + y + i * 8) * DMODEL + nt + x];
    __syncthreads();
#pragma unroll
    for (int i = 0; i < 4; i++) {
        float v = t[x][y + i * 8];
        __half h = __float2half(v);
        size_t o = (size_t)(nt + y + i * 8) * DMODEL + kt + x;
        hi[o] = h;
        if (wlo) vlo[o] = __float2half(v - __half2float(h));
    }
}

// =================================================================
// fp16 GEMM via mma.sync.  CTA 128x64, BK=32, 8 warps (4m x 2n).
// MODE 0 (Wo): plain A x plain B, 1 MMA, fp32 out + bias.
// MODE 1 (QKV): Q,K slots plain (1 MMA); V slot split A + W correction
//               (3 MMA).  fp16 out; lo written for V slot only.
// 2 CTAs/SM target.
// =================================================================
#define ST_A   (128 * 80)             // 10240 B per A matrix
#define ST_B   (64 * 80)              // 5120 B per B matrix
#define ST_SZ  (2 * ST_A + 2 * ST_B)  // 30720 B per stage
#define OFF_ALO ST_A
#define OFF_BHI (2 * ST_A)
#define OFF_BLO (2 * ST_A + ST_B)

template <int MODE>
__global__ __launch_bounds__(256, 2) void gemm_mma_kernel(
    const __half* __restrict__ Ahi, const __half* __restrict__ Alo,
    const __half* __restrict__ Bhi, const __half* __restrict__ Blo,
    const float* __restrict__ bias, float* __restrict__ C,
    __half* __restrict__ Ch, __half* __restrict__ Cl,
    int M, int N, int K)
{
    extern __shared__ __align__(128) char smem[];
    const uint32_t sb = smem_u32(smem);
    const int tid = threadIdx.x;
    const int wid = tid >> 5, lane = tid & 31;
    const int wm = wid & 3, wn = wid >> 2;
    const int m0 = blockIdx.y * 128, n0 = blockIdx.x * 64;
    const int lrow = lane & 15, lcolb = (lane >> 4) * 16;
    const bool vslot = (MODE == 1) && (n0 >= 2 * DMODEL);   // split path

    float acc[2][4][4];
#pragma unroll
    for (int mt = 0; mt < 2; mt++)
#pragma unroll
        for (int nt = 0; nt < 4; nt++)
#pragma unroll
            for (int j = 0; j < 4; j++) acc[mt][nt][j] = 0.f;

    const int nchunks = K >> 5;

    auto issue = [&](int c) {
        const int k0 = c << 5;
        const uint32_t st = sb + (uint32_t)((c & 1) * ST_SZ);
#pragma unroll
        for (int i = 0; i < 2; i++) {
            int idx = tid + i * 256;          // 0..511
            int r = idx >> 2, kc = idx & 3;
            size_t go = (size_t)(m0 + r) * K + k0 + kc * 8;
            uint32_t so = (uint32_t)(r * 80 + kc * 16);
            cp16(st + so, Ahi + go);
            if (vslot) cp16(st + OFF_ALO + so, Alo + go);
        }
        {
            int r = tid >> 2, kc = tid & 3;
            size_t go = (size_t)(n0 + r) * K + k0 + kc * 8;
            uint32_t so = (uint32_t)(r * 80 + kc * 16);
            cp16(st + OFF_BHI + so, Bhi + go);
            if (vslot) {
                // Blo (g_wvlo) is V-local [1024,K]: subtract the slot base
                size_t gol = (size_t)(n0 - 2 * DMODEL + r) * K + k0 + kc * 8;
                cp16(st + OFF_BLO + so, Blo + gol);
            }
        }
        CP_COMMIT();
    };

    issue(0);
    issue(1);

    for (int c = 0; c < nchunks; c++) {
        if (c + 1 < nchunks) CP_WAIT1(); else CP_WAIT0();
        __syncthreads();

        const uint32_t st = sb + (uint32_t)((c & 1) * ST_SZ);
        const uint32_t aHi = st + (uint32_t)((wm * 32 + lrow) * 80) + lcolb;
        const uint32_t aLo = aHi + OFF_ALO;
        const uint32_t bHi = st + OFF_BHI + (uint32_t)((wn * 32 + lrow) * 80) + lcolb;
        const uint32_t bLo = bHi + ST_B;

#pragma unroll
        for (int ks = 0; ks < 2; ks++) {
            const uint32_t kb = ks * 32;
            uint32_t ah[2][4];
#pragma unroll
            for (int mt = 0; mt < 2; mt++)
                ldm_x4(ah[mt][0], ah[mt][1], ah[mt][2], ah[mt][3],
                       aHi + (uint32_t)(mt * 16 * 80) + kb);
            uint32_t bh[4][2];
#pragma unroll
            for (int g = 0; g < 2; g++) {
                uint32_t r0, r1, r2, r3;
                ldm_x4(r0, r1, r2, r3, bHi + (uint32_t)(g * 16 * 80) + kb);
                bh[2 * g + 0][0] = r0; bh[2 * g + 0][1] = r2;
                bh[2 * g + 1][0] = r1; bh[2 * g + 1][1] = r3;
            }
#pragma unroll
            for (int mt = 0; mt < 2; mt++)
#pragma unroll
                for (int nt = 0; nt < 4; nt++)
                    mma_f16(acc[mt][nt], ah[mt], bh[nt][0], bh[nt][1]);

            if (vslot) {
                uint32_t al[2][4];
#pragma unroll
                for (int mt = 0; mt < 2; mt++)
                    ldm_x4(al[mt][0], al[mt][1], al[mt][2], al[mt][3],
                           aLo + (uint32_t)(mt * 16 * 80) + kb);
                uint32_t bl[4][2];
#pragma unroll
                for (int g = 0; g < 2; g++) {
                    uint32_t r0, r1, r2, r3;
                    ldm_x4(r0, r1, r2, r3, bLo + (uint32_t)(g * 16 * 80) + kb);
                    bl[2 * g + 0][0] = r0; bl[2 * g + 0][1] = r2;
                    bl[2 * g + 1][0] = r1; bl[2 * g + 1][1] = r3;
                }
#pragma unroll
                for (int mt = 0; mt < 2; mt++)
#pragma unroll
                    for (int nt = 0; nt < 4; nt++) {
                        mma_f16(acc[mt][nt], al[mt], bh[nt][0], bh[nt][1]);
                        mma_f16(acc[mt][nt], ah[mt], bl[nt][0], bl[nt][1]);
                    }
            }
        }
        __syncthreads();
        if (c + 2 < nchunks) issue(c + 2);
    }

    const int rbase = m0 + wm * 32 + (lane >> 2);
    const int cb0 = n0 + wn * 32 + 2 * (lane & 3);
#pragma unroll
    for (int mt = 0; mt < 2; mt++)
#pragma unroll
        for (int nt = 0; nt < 4; nt++) {
            int col = cb0 + nt * 8;
            int r0 = rbase + mt * 16;
            if (MODE == 0) {
                float b0 = bias[col], b1 = bias[col + 1];
                float2 v0 = { acc[mt][nt][0] + b0, acc[mt][nt][1] + b1 };
                float2 v1 = { acc[mt][nt][2] + b0, acc[mt][nt][3] + b1 };
                *(float2*)&C[(size_t)r0 * N + col] = v0;
                *(float2*)&C[(size_t)(r0 + 8) * N + col] = v1;
            } else {
                int slot = col >> 10, coll = col & 1023;
                size_t obh = (size_t)slot * SLOTSZ + (size_t)coll;
#pragma unroll
                for (int half = 0; half < 2; half++) {
                    int rr = r0 + half * 8;
                    float v0 = acc[mt][nt][2 * half], v1 = acc[mt][nt][2 * half + 1];
                    __half h0 = __float2half(v0), h1 = __float2half(v1);
                    __half2 hp; hp.x = h0; hp.y = h1;
                    *(__half2*)&Ch[obh + (size_t)rr * DMODEL] = hp;
                    if (vslot) {
                        __half2 lp;
                        lp.x = __float2half(v0 - __half2float(h0));
                        lp.y = __float2half(v1 - __half2float(h1));
                        *(__half2*)&Cl[(size_t)coll + (size_t)rr * DMODEL] = lp;
                    }
                }
            }
        }
}

// =================================================================
// Tensor-core flash attention, fp16.  2 CTAs/SM target.
// Scores: Q plain x K plain (1 MMA).  PV: P plain, V split (2 MMA).
// CTA: 128 queries x one (b,h).  8 warps x 16 q-rows.  K/V tiles 64.
// Stage: K | Vh | Vl (3 mats, 27648 B), 2 stages.
// =================================================================
#define AT_ROW 144
#define AT_MAT (64 * AT_ROW)          // 9216
#define AT_STAGE (3 * AT_MAT)         // 27648
#define ASCALE 0.03125f

__global__ __launch_bounds__(256, 2) void attn_mma_kernel(
    const __half* __restrict__ qkvh,
    const __half* __restrict__ vlo,
    __half* __restrict__ oh)
{
    extern __shared__ __align__(128) char smem[];
    const uint32_t sb = smem_u32(smem);
    const int tid = threadIdx.x;
    const int wid = tid >> 5, lane = tid & 31;
    const int q0 = (int)(gridDim.x - 1 - blockIdx.x) * 128;
    const int h = blockIdx.y, b = blockIdx.z;

    const size_t base = (size_t)(b * SDIM) * DMODEL + h * HDIM;
    const __half* Qh = qkvh + base;
    const __half* Kh = qkvh + SLOTSZ + base;
    const __half* Vh = qkvh + 2 * SLOTSZ + base;
    const __half* Vl = vlo + base;

    // ---- stage Q through smem, extract frags ----
#pragma unroll
    for (int i = 0; i < 2; i++) {
        int idx = tid + i * 256;               // 0..511
        int r = idx >> 2, c = idx & 3;
        size_t go = (size_t)(q0 + r) * DMODEL + c * 16;
        uint32_t so = (uint32_t)(r * AT_ROW + c * 32);
        cp16(sb + so, Qh + go);
        cp16(sb + so + 16, Qh + go + 8);
    }
    CP_COMMIT(); CP_WAIT0();
    __syncthreads();

    uint32_t qf[4][4];
    {
        uint32_t qa = sb + (uint32_t)((wid * 16 + (lane & 15)) * AT_ROW)
                         + (uint32_t)((lane >> 4) * 16);
#pragma unroll
        for (int ks = 0; ks < 4; ks++)
            ldm_x4(qf[ks][0], qf[ks][1], qf[ks][2], qf[ks][3], qa + ks * 32);
    }
    __syncthreads();

    auto issue = [&](int it) {
        const int k0 = it * 64;
        const uint32_t st = sb + (uint32_t)((it & 1) * AT_STAGE);
#pragma unroll
        for (int i = 0; i < 2; i++) {
            int idx = tid + i * 256;           // 0..511
            int r = idx >> 3, c = idx & 7;
            size_t go = (size_t)(k0 + r) * DMODEL + c * 8;
            uint32_t so = (uint32_t)(r * AT_ROW + c * 16);
            cp16(st + 0 * AT_MAT + so, Kh + go);
            cp16(st + 1 * AT_MAT + so, Vh + go);
            cp16(st + 2 * AT_MAT + so, Vl + go);
        }
        CP_COMMIT();
    };

    float m_r[2] = { -1e30f, -1e30f };
    float l_r[2] = { 0.f, 0.f };
    float oc[8][4];
#pragma unroll
    for (int j = 0; j < 8; j++)
#pragma unroll
        for (int v = 0; v < 4; v++) oc[j][v] = 0.f;

    const int niters = (q0 >> 6) + 2;
    issue(0);
    if (niters > 1) issue(1);

    const int r0g = q0 + wid * 16 + (lane >> 2);
    const int r1g = r0g + 8;
    const int wrow_max = q0 + wid * 16 + 15;

    for (int it = 0; it < niters; it++) {
        if (it + 1 < niters) CP_WAIT1(); else CP_WAIT0();
        __syncthreads();
        const int k0 = it * 64;

        if (k0 <= wrow_max) {
            const uint32_t st = sb + (uint32_t)((it & 1) * AT_STAGE);
            const uint32_t kHi = st + (uint32_t)((lane & 15) * AT_ROW)
                                    + (uint32_t)((lane >> 4) * 16);
            const uint32_t vHi = st + 1 * AT_MAT + (uint32_t)((lane & 15) * AT_ROW)
                                    + (uint32_t)((lane >> 4) * 16);
            const uint32_t vLo = vHi + AT_MAT;

            // ---- S = Q @ K^T (plain, 1 MMA) ----
            float sc[8][4];
#pragma unroll
            for (int j = 0; j < 8; j++)
#pragma unroll
                for (int v = 0; v < 4; v++) sc[j][v] = 0.f;

#pragma unroll
            for (int ks = 0; ks < 4; ks++) {
                uint32_t bh[8][2];
#pragma unroll
                for (int g = 0; g < 4; g++) {
                    uint32_t r0, r1, r2, r3;
                    ldm_x4(r0, r1, r2, r3, kHi + (uint32_t)(g * 16 * AT_ROW) + ks * 32);
                    bh[2 * g + 0][0] = r0; bh[2 * g + 0][1] = r2;
                    bh[2 * g + 1][0] = r1; bh[2 * g + 1][1] = r3;
                }
#pragma unroll
                for (int j = 0; j < 8; j++)
                    mma_f16(sc[j], qf[ks], bh[j][0], bh[j][1]);
            }

            // ---- mask + scale ----
            const int cb = k0 + 2 * (lane & 3);
#pragma unroll
            for (int j = 0; j < 8; j++) {
                int c0 = cb + 8 * j, c1 = c0 + 1;
                sc[j][0] = (c0 <= r0g) ? sc[j][0] * ASCALE : -1e30f;
                sc[j][1] = (c1 <= r0g) ? sc[j][1] * ASCALE : -1e30f;
                sc[j][2] = (c0 <= r1g) ? sc[j][2] * ASCALE : -1e30f;
                sc[j][3] = (c1 <= r1g) ? sc[j][3] * ASCALE : -1e30f;
            }

            // ---- online softmax ----
            float mt0 = -1e30f, mt1 = -1e30f;
#pragma unroll
            for (int j = 0; j < 8; j++) {
                mt0 = fmaxf(mt0, fmaxf(sc[j][0], sc[j][1]));
                mt1 = fmaxf(mt1, fmaxf(sc[j][2], sc[j][3]));
            }
            mt0 = fmaxf(mt0, __shfl_xor_sync(0xffffffffu, mt0, 1));
            mt0 = fmaxf(mt0, __shfl_xor_sync(0xffffffffu, mt0, 2));
            mt1 = fmaxf(mt1, __shfl_xor_sync(0xffffffffu, mt1, 1));
            mt1 = fmaxf(mt1, __shfl_xor_sync(0xffffffffu, mt1, 2));
            float mn0 = fmaxf(m_r[0], mt0), mn1 = fmaxf(m_r[1], mt1);
            float a0 = __expf(m_r[0] - mn0), a1 = __expf(m_r[1] - mn1);
            m_r[0] = mn0; m_r[1] = mn1;

            float s0 = 0.f, s1 = 0.f;
            // ---- exp + pack plain P IN PLACE over sc ----
#pragma unroll
            for (int j = 0; j < 8; j++) {
                float e0 = __expf(sc[j][0] - mn0);
                float e1 = __expf(sc[j][1] - mn0);
                float e2 = __expf(sc[j][2] - mn1);
                float e3 = __expf(sc[j][3] - mn1);
                s0 += e0 + e1; s1 += e2 + e3;
                sc[j][0] = __uint_as_float(packh(e0, e1));   // P rows 0-7
                sc[j][1] = __uint_as_float(packh(e2, e3));   // P rows 8-15
            }
            l_r[0] = l_r[0] * a0 + s0;
            l_r[1] = l_r[1] * a1 + s1;
#pragma unroll
            for (int j = 0; j < 8; j++) {
                oc[j][0] *= a0; oc[j][1] *= a0;
                oc[j][2] *= a1; oc[j][3] *= a1;
            }

            // ---- O += P @ V (P plain, V split: 2 MMAs) ----
#pragma unroll
            for (int ks = 0; ks < 4; ks++) {
                uint32_t vh[8][2], vl[8][2];
#pragma unroll
                for (int g = 0; g < 4; g++) {
                    uint32_t r0, r1, r2, r3;
                    ldm_x4t(r0, r1, r2, r3, vHi + (uint32_t)(ks * 16 * AT_ROW) + g * 32);
                    vh[2 * g + 0][0] = r0; vh[2 * g + 0][1] = r1;
                    vh[2 * g + 1][0] = r2; vh[2 * g + 1][1] = r3;
                    ldm_x4t(r0, r1, r2, r3, vLo + (uint32_t)(ks * 16 * AT_ROW) + g * 32);
                    vl[2 * g + 0][0] = r0; vl[2 * g + 0][1] = r1;
                    vl[2 * g + 1][0] = r2; vl[2 * g + 1][1] = r3;
                }
                uint32_t pa[4] = { __float_as_uint(sc[2 * ks][0]),
                                   __float_as_uint(sc[2 * ks][1]),
                                   __float_as_uint(sc[2 * ks + 1][0]),
                                   __float_as_uint(sc[2 * ks + 1][1]) };
#pragma unroll
                for (int j = 0; j < 8; j++) {
                    mma_f16(oc[j], pa, vh[j][0], vh[j][1]);
                    mma_f16(oc[j], pa, vl[j][0], vl[j][1]);
                }
            }
        }

        __syncthreads();
        if (it + 2 < niters) issue(it + 2);
    }

    // ---- epilogue (hi only) ----
    float lt0 = l_r[0];
    lt0 += __shfl_xor_sync(0xffffffffu, lt0, 1);
    lt0 += __shfl_xor_sync(0xffffffffu, lt0, 2);
    float lt1 = l_r[1];
    lt1 += __shfl_xor_sync(0xffffffffu, lt1, 1);
    lt1 += __shfl_xor_sync(0xffffffffu, lt1, 2);
    float inv0 = 1.f / lt0, inv1 = 1.f / lt1;

    size_t ob0 = (size_t)(b * SDIM + r0g) * DMODEL + h * HDIM + 2 * (lane & 3);
    size_t ob1 = ob0 + (size_t)8 * DMODEL;
#pragma unroll
    for (int j = 0; j < 8; j++) {
        __half2 hp0 = __floats2half2_rn(oc[j][0] * inv0, oc[j][1] * inv0);
        __half2 hp1 = __floats2half2_rn(oc[j][2] * inv1, oc[j][3] * inv1);
        *(__half2*)&oh[ob0 + 8 * j] = hp0;
        *(__half2*)&oh[ob1 + 8 * j] = hp1;
    }
}

// =================================================================
extern "C" void kernel_launch(void* const* d_in, const int* in_sizes, int n_in,
                              void* d_out, int out_size)
{
    const float* x  = (const float*)d_in[0];
    const float* Wq = (const float*)d_in[1];
    const float* Wk = (const float*)d_in[2];
    const float* Wv = (const float*)d_in[3];
    const float* Wo = (const float*)d_in[4];
    const float* bo = (const float*)d_in[5];
    float* out = (float*)d_out;

    __half *pxh, *pxl, *pqkvh, *pqkvl, *pah, *pwh, *pwvlo;
    cudaGetSymbolAddress((void**)&pxh, g_xhi);
    cudaGetSymbolAddress((void**)&pxl, g_xlo);
    cudaGetSymbolAddress((void**)&pqkvh, g_qkvh);
    cudaGetSymbolAddress((void**)&pqkvl, g_qkvl);
    cudaGetSymbolAddress((void**)&pah, g_ah);
    cudaGetSymbolAddress((void**)&pwh, g_whi);
    cudaGetSymbolAddress((void**)&pwvlo, g_wvlo);

    const int NEL = MTOT * DMODEL;

    split_kernel<<<NEL / (256 * 4), 256>>>(x, pxh, pxl, NEL);
    dim3 tgrid(DMODEL / 32, DMODEL / 32, 4), tblk(32, 8);
    tsplit_all_kernel<<<tgrid, tblk>>>(Wq, Wk, Wv, Wo, pwh, pwvlo);

    const int gsmem = 2 * ST_SZ;   // 61440
    cudaFuncSetAttribute(gemm_mma_kernel<0>,
                         cudaFuncAttributeMaxDynamicSharedMemorySize, gsmem);
    cudaFuncSetAttribute(gemm_mma_kernel<1>,
                         cudaFuncAttributeMaxDynamicSharedMemorySize, gsmem);

    // fused QKV projection: N = 3072
    dim3 gq(3 * DMODEL / 64, MTOT / 128);   // (48, 32)
    gemm_mma_kernel<1><<<gq, 256, gsmem>>>(pxh, pxl, pwh, pwvlo,
                                           nullptr, nullptr, pqkvh, pqkvl,
                                           MTOT, 3 * DMODEL, DMODEL);

    const int asmem = 2 * AT_STAGE;         // 55296
    cudaFuncSetAttribute(attn_mma_kernel,
                         cudaFuncAttributeMaxDynamicSharedMemorySize, asmem);
    dim3 agrid(SDIM / 128, NHEADS, BATCH);  // (16, 16, 2)
    attn_mma_kernel<<<agrid, 256, asmem>>>(pqkvh, pqkvl, pah);

    dim3 go(DMODEL / 64, MTOT / 128);       // (16, 32)
    gemm_mma_kernel<0><<<go, 256, gsmem>>>(pah, nullptr, pwh + 3 * WEL, nullptr,
                                           bo, out, nullptr, nullptr,
                                           MTOT, DMODEL, DMODEL);
}